// round 1
// baseline (speedup 1.0000x reference)
#include <cuda_runtime.h>
#include <cuda_bf16.h>
#include <math.h>

// ---------------------------------------------------------------------------
// Problem constants
// ---------------------------------------------------------------------------
#define Cdim   1024
#define Hn     16
#define DH     64
#define DFF    4096
#define Ddim   1024
#define Bn     2
#define Ln     2048
#define ROWS   (Bn * Ln)          // 4096
#define MAX_SCALE_MUL 4.605170185988092f
#define LN_EPS 1e-6f

// ---------------------------------------------------------------------------
// Scratch (device globals; no runtime allocation allowed)
// ---------------------------------------------------------------------------
__device__ float g_silu[Bn * Ddim];          // SiLU(cond)
__device__ float g_ada [Bn * 6 * Cdim];      // adaLN outputs [B,6C]
__device__ float g_h   [ROWS * Cdim];        // modulated LN activations
__device__ float g_qkv [ROWS * 3 * Cdim];    // qkv
__device__ float g_attn[ROWS * Cdim];        // attention output (pre-proj)
__device__ float g_ffn [ROWS * DFF];         // fc1 output

// ---------------------------------------------------------------------------
// Small helpers
// ---------------------------------------------------------------------------
__device__ __forceinline__ float warp_sum(float v) {
    #pragma unroll
    for (int o = 16; o; o >>= 1) v += __shfl_xor_sync(0xFFFFFFFFu, v, o);
    return v;
}
__device__ __forceinline__ float warp_max(float v) {
    #pragma unroll
    for (int o = 16; o; o >>= 1) v = fmaxf(v, __shfl_xor_sync(0xFFFFFFFFu, v, o));
    return v;
}
__device__ __forceinline__ float block_sum(float v, float* red) {
    __syncthreads();                       // protect red reuse
    int lane = threadIdx.x & 31, w = threadIdx.x >> 5;
    v = warp_sum(v);
    if (lane == 0) red[w] = v;
    __syncthreads();
    if (w == 0) {
        float x = (lane < (int)(blockDim.x >> 5)) ? red[lane] : 0.f;
        x = warp_sum(x);
        if (lane == 0) red[0] = x;
    }
    __syncthreads();
    return red[0];
}

// ---------------------------------------------------------------------------
// SiLU(cond)
// ---------------------------------------------------------------------------
__global__ void silu_kernel(const float* __restrict__ cond) {
    int i = blockIdx.x * blockDim.x + threadIdx.x;
    if (i < Bn * Ddim) {
        float v = cond[i];
        g_silu[i] = v / (1.f + expf(-v));
    }
}

// ---------------------------------------------------------------------------
// ada = silu(cond) @ ada_w^T + ada_b     (one warp per output element)
// ---------------------------------------------------------------------------
__global__ void ada_kernel(const float* __restrict__ ada_w,
                           const float* __restrict__ ada_b) {
    int gw   = (blockIdx.x * blockDim.x + threadIdx.x) >> 5;
    int lane = threadIdx.x & 31;
    if (gw >= Bn * 6 * Cdim) return;
    int b = gw / (6 * Cdim), j = gw % (6 * Cdim);
    const float* wv = ada_w + (size_t)j * Ddim;
    const float* sv = g_silu + b * Ddim;
    float acc = 0.f;
    #pragma unroll 2
    for (int i = lane * 4; i < Ddim; i += 128) {
        float4 w4 = *(const float4*)(wv + i);
        float4 s4 = *(const float4*)(sv + i);
        acc += w4.x * s4.x + w4.y * s4.y + w4.z * s4.z + w4.w * s4.w;
    }
    acc = warp_sum(acc);
    if (lane == 0) g_ada[b * 6 * Cdim + j] = acc + ada_b[j];
}

// ---------------------------------------------------------------------------
// h = LN(x) * (s+1) + sh      (one block of 256 threads per row)
// ---------------------------------------------------------------------------
__global__ void ln_mod_kernel(const float* __restrict__ x, float* __restrict__ h,
                              int sChunk, int shChunk) {
    __shared__ float red[32];
    int row = blockIdx.x;
    int b   = row >> 11;
    const float* xr = x + (size_t)row * Cdim;
    int c = threadIdx.x * 4;
    float4 v = *(const float4*)(xr + c);
    float tot  = block_sum(v.x + v.y + v.z + v.w, red);
    float mean = tot * (1.f / Cdim);
    float dx = v.x - mean, dy = v.y - mean, dz = v.z - mean, dw = v.w - mean;
    float tss  = block_sum(dx * dx + dy * dy + dz * dz + dw * dw, red);
    float rstd = rsqrtf(tss * (1.f / Cdim) + LN_EPS);
    const float* sP  = g_ada + b * 6 * Cdim + sChunk  * Cdim;
    const float* shP = g_ada + b * 6 * Cdim + shChunk * Cdim;
    float4 s4  = *(const float4*)(sP  + c);
    float4 sh4 = *(const float4*)(shP + c);
    float4 o;
    o.x = dx * rstd * (s4.x + 1.f) + sh4.x;
    o.y = dy * rstd * (s4.y + 1.f) + sh4.y;
    o.z = dz * rstd * (s4.z + 1.f) + sh4.z;
    o.w = dw * rstd * (s4.w + 1.f) + sh4.w;
    *(float4*)(h + (size_t)row * Cdim + c) = o;
}

// ---------------------------------------------------------------------------
// Generic tiled SGEMM: C[M,N] = A[M,K] @ W[N,K]^T  (+ fused epilogue)
//   MODE 0: QKV   (bias = concat(q_bias, 0, v_bias)) -> g_qkv
//   MODE 1: PROJ  (out = res + (acc + pb)*g1)        -> d_out
//   MODE 2: FC1   (out = gelu_tanh(acc + b))         -> g_ffn
//   MODE 3: FC2   (out = Cexisting + (acc + b)*g2)   -> d_out (in place)
// ---------------------------------------------------------------------------
#define BM 128
#define BN 128
#define BK 16

template <int MODE>
__global__ __launch_bounds__(256, 2)
void gemm_kernel(const float* __restrict__ A, const float* __restrict__ W,
                 float* __restrict__ C, int M, int N, int K,
                 const float* __restrict__ bias,
                 const float* __restrict__ bias2,
                 const float* __restrict__ res) {
    __shared__ float As[BK][BM + 4];
    __shared__ float Ws[BK][BN + 4];

    int tx = threadIdx.x & 15, ty = threadIdx.x >> 4;
    int m0 = blockIdx.y * BM, n0 = blockIdx.x * BN;

    float acc[8][8];
    #pragma unroll
    for (int i = 0; i < 8; i++)
        #pragma unroll
        for (int j = 0; j < 8; j++) acc[i][j] = 0.f;

    for (int kt = 0; kt < K; kt += BK) {
        #pragma unroll
        for (int r = 0; r < 2; r++) {
            int idx = threadIdx.x + r * 256;     // 0..511
            int m   = idx >> 2;                  // 0..127
            int k4  = (idx & 3) << 2;            // 0,4,8,12
            float4 av = *(const float4*)(A + (size_t)(m0 + m) * K + kt + k4);
            As[k4 + 0][m] = av.x; As[k4 + 1][m] = av.y;
            As[k4 + 2][m] = av.z; As[k4 + 3][m] = av.w;
            float4 wv = *(const float4*)(W + (size_t)(n0 + m) * K + kt + k4);
            Ws[k4 + 0][m] = wv.x; Ws[k4 + 1][m] = wv.y;
            Ws[k4 + 2][m] = wv.z; Ws[k4 + 3][m] = wv.w;
        }
        __syncthreads();
        #pragma unroll
        for (int kk = 0; kk < BK; kk++) {
            float a[8], b[8];
            *(float4*)&a[0] = *(const float4*)&As[kk][ty * 8];
            *(float4*)&a[4] = *(const float4*)&As[kk][ty * 8 + 4];
            *(float4*)&b[0] = *(const float4*)&Ws[kk][tx * 8];
            *(float4*)&b[4] = *(const float4*)&Ws[kk][tx * 8 + 4];
            #pragma unroll
            for (int i = 0; i < 8; i++)
                #pragma unroll
                for (int j = 0; j < 8; j++) acc[i][j] += a[i] * b[j];
        }
        __syncthreads();
    }

    int b_idx = m0 >> 11;   // batch (rows of tile never cross the 2048 boundary)
    #pragma unroll
    for (int i = 0; i < 8; i++) {
        int row = m0 + ty * 8 + i;
        float* crow = C + (size_t)row * N + n0 + tx * 8;
        float out[8];
        #pragma unroll
        for (int j = 0; j < 8; j++) {
            int n = n0 + tx * 8 + j;
            float v = acc[i][j];
            if (MODE == 0) {            // QKV
                float bb = (n < Cdim) ? bias[n]
                         : (n < 2 * Cdim) ? 0.f : bias2[n - 2 * Cdim];
                out[j] = v + bb;
            } else if (MODE == 1) {     // PROJ
                float g1 = g_ada[b_idx * 6 * Cdim + 0 * Cdim + n];
                out[j] = res[(size_t)row * Cdim + n] + (v + bias[n]) * g1;
            } else if (MODE == 2) {     // FC1 + gelu(tanh)
                float xg = v + bias[n];
                float t  = tanhf(0.7978845608028654f * (xg + 0.044715f * xg * xg * xg));
                out[j] = 0.5f * xg * (1.f + t);
            } else {                    // FC2 + residual*g2 (in place on C)
                float g2 = g_ada[b_idx * 6 * Cdim + 1 * Cdim + n];
                out[j] = crow[j] + (v + bias[n]) * g2;
            }
        }
        *(float4*)(crow)     = *(float4*)&out[0];
        *(float4*)(crow + 4) = *(float4*)&out[4];
    }
}

// ---------------------------------------------------------------------------
// Normalize q,k per (row, head): q *= rsqrt(max(|q|^2,1e-24)) * exp(min(sm,log100))
// one warp per (row, head)
// ---------------------------------------------------------------------------
__global__ void norm_qk_kernel(const float* __restrict__ scale_mul) {
    int gw   = (blockIdx.x * blockDim.x + threadIdx.x) >> 5;
    int lane = threadIdx.x & 31;
    if (gw >= ROWS * Hn) return;
    int row = gw >> 4, h = gw & 15;
    float sm = expf(fminf(scale_mul[h], MAX_SCALE_MUL));
    float* q = g_qkv + (size_t)row * (3 * Cdim) + h * DH;
    float* k = q + Cdim;

    float2 qv = *(float2*)(q + lane * 2);
    float  sq = warp_sum(qv.x * qv.x + qv.y * qv.y);
    float  rq = rsqrtf(fmaxf(sq, 1e-24f)) * sm;
    qv.x *= rq; qv.y *= rq;
    *(float2*)(q + lane * 2) = qv;

    float2 kv = *(float2*)(k + lane * 2);
    float  sk = warp_sum(kv.x * kv.x + kv.y * kv.y);
    float  rk = rsqrtf(fmaxf(sk, 1e-24f));
    kv.x *= rk; kv.y *= rk;
    *(float2*)(k + lane * 2) = kv;
}

// ---------------------------------------------------------------------------
// Flash-style attention: block = (qtile=64, h, b); 8 warps x 8 q-rows each.
// Online softmax over 32 K/V tiles of 64. Bias streamed from gmem.
// ---------------------------------------------------------------------------
#define QT 64
#define KT 64
#define SROW 68   // padded smem row stride

__global__ __launch_bounds__(256, 1)
void attn_kernel(const float* __restrict__ attn_bias) {
    extern __shared__ float smem[];
    float* Qs   = smem;                   // 64 x SROW
    float* Ks   = Qs + QT * SROW;
    float* Vs   = Ks + KT * SROW;
    float* pbuf = Vs + KT * SROW;         // 8 x 64

    int t    = threadIdx.x;
    int w    = t >> 5, lane = t & 31;
    int qt   = blockIdx.x, h = blockIdx.y, b = blockIdx.z;
    int qbase = b * Ln + qt * QT;         // global row of first q

    // Load normalized Q tile
    #pragma unroll
    for (int r = 0; r < 4; r++) {
        int idx = t + r * 256;            // 0..1023
        int qr  = idx >> 4;
        int c4  = (idx & 15) << 2;
        float4 v = *(const float4*)(g_qkv + (size_t)(qbase + qr) * (3 * Cdim) + h * DH + c4);
        *(float4*)&Qs[qr * SROW + c4] = v;
    }

    float m[8], l[8], o0[8], o1[8];
    #pragma unroll
    for (int r = 0; r < 8; r++) { m[r] = -1e30f; l[r] = 0.f; o0[r] = 0.f; o1[r] = 0.f; }

    int kj0 = 2 * lane, kj1 = 2 * lane + 1;

    for (int kt = 0; kt < Ln / KT; kt++) {
        __syncthreads();
        int kbase_row = b * Ln + kt * KT;
        #pragma unroll
        for (int r = 0; r < 4; r++) {
            int idx = t + r * 256;
            int kr  = idx >> 4;
            int c4  = (idx & 15) << 2;
            size_t base = (size_t)(kbase_row + kr) * (3 * Cdim) + h * DH + c4;
            float4 kv = *(const float4*)(g_qkv + base + Cdim);
            float4 vv = *(const float4*)(g_qkv + base + 2 * Cdim);
            *(float4*)&Ks[kr * SROW + c4] = kv;
            *(float4*)&Vs[kr * SROW + c4] = vv;
        }
        __syncthreads();

        int kcol = kt * KT;
        #pragma unroll 1
        for (int r = 0; r < 8; r++) {
            int qr = w * 8 + r;
            int gq = qt * QT + qr;
            const float* qp = &Qs[qr * SROW];
            const float* k0 = &Ks[kj0 * SROW];
            const float* k1 = &Ks[kj1 * SROW];
            float s0 = 0.f, s1 = 0.f;
            #pragma unroll
            for (int d = 0; d < DH; d += 4) {
                float4 q4 = *(const float4*)(qp + d);
                float4 a4 = *(const float4*)(k0 + d);
                float4 b4 = *(const float4*)(k1 + d);
                s0 += q4.x * a4.x + q4.y * a4.y + q4.z * a4.z + q4.w * a4.w;
                s1 += q4.x * b4.x + q4.y * b4.y + q4.z * b4.z + q4.w * b4.w;
            }
            const float* brow = attn_bias + (size_t)gq * Ln + kcol;
            s0 += brow[kj0];
            s1 += brow[kj1];

            float tm = warp_max(fmaxf(s0, s1));
            float nm = fmaxf(m[r], tm);
            float alpha = __expf(m[r] - nm);
            float p0 = __expf(s0 - nm), p1 = __expf(s1 - nm);
            float ts = warp_sum(p0 + p1);
            l[r] = l[r] * alpha + ts;
            o0[r] *= alpha; o1[r] *= alpha;
            m[r] = nm;

            pbuf[w * 64 + kj0] = p0;
            pbuf[w * 64 + kj1] = p1;
            __syncwarp();
            float a0 = 0.f, a1 = 0.f;
            #pragma unroll
            for (int kj = 0; kj < KT; kj++) {
                float p = pbuf[w * 64 + kj];
                float2 v2 = *(const float2*)&Vs[kj * SROW + 2 * lane];
                a0 += p * v2.x;
                a1 += p * v2.y;
            }
            o0[r] += a0; o1[r] += a1;
            __syncwarp();
        }
    }

    #pragma unroll
    for (int r = 0; r < 8; r++) {
        int grow = qbase + w * 8 + r;
        float inv = 1.f / l[r];
        float2 ov; ov.x = o0[r] * inv; ov.y = o1[r] * inv;
        *(float2*)(g_attn + (size_t)grow * Cdim + h * DH + 2 * lane) = ov;
    }
}

// ---------------------------------------------------------------------------
// Launch
// ---------------------------------------------------------------------------
extern "C" void kernel_launch(void* const* d_in, const int* in_sizes, int n_in,
                              void* d_out, int out_size) {
    const float* x         = (const float*)d_in[0];
    const float* cond      = (const float*)d_in[1];
    const float* attn_bias = (const float*)d_in[2];
    const float* qkv_w     = (const float*)d_in[3];
    const float* q_bias    = (const float*)d_in[4];
    const float* v_bias    = (const float*)d_in[5];
    const float* scale_mul = (const float*)d_in[6];
    const float* proj_w    = (const float*)d_in[7];
    const float* proj_b    = (const float*)d_in[8];
    const float* fc1_w     = (const float*)d_in[9];
    const float* fc1_b     = (const float*)d_in[10];
    const float* fc2_w     = (const float*)d_in[11];
    const float* fc2_b     = (const float*)d_in[12];
    const float* ada_w     = (const float*)d_in[13];
    const float* ada_b     = (const float*)d_in[14];
    float* out = (float*)d_out;

    float* gqkvP;  cudaGetSymbolAddress((void**)&gqkvP,  g_qkv);
    float* ghP;    cudaGetSymbolAddress((void**)&ghP,    g_h);
    float* gattnP; cudaGetSymbolAddress((void**)&gattnP, g_attn);
    float* gffnP;  cudaGetSymbolAddress((void**)&gffnP,  g_ffn);

    static int attn_smem_set = 0;
    int attn_smem = (3 * QT * SROW + 8 * 64) * (int)sizeof(float);  // 54.3 KB
    cudaFuncSetAttribute(attn_kernel, cudaFuncAttributeMaxDynamicSharedMemorySize, attn_smem);
    (void)attn_smem_set;

    // 1) SiLU(cond)
    silu_kernel<<<(Bn * Ddim + 255) / 256, 256>>>(cond);
    // 2) adaLN linear
    ada_kernel<<<(Bn * 6 * Cdim * 32 + 255) / 256, 256>>>(ada_w, ada_b);
    // 3) h = LN(x)*(s1+1)+sh1
    ln_mod_kernel<<<ROWS, 256>>>(x, ghP, 2, 4);
    // 4) qkv = h @ qkv_w^T + bias
    gemm_kernel<0><<<dim3(3 * Cdim / BN, ROWS / BM), 256>>>(
        ghP, qkv_w, gqkvP, ROWS, 3 * Cdim, Cdim, q_bias, v_bias, nullptr);
    // 5) normalize q,k
    norm_qk_kernel<<<(ROWS * Hn * 32 + 255) / 256, 256>>>(scale_mul);
    // 6) attention
    attn_kernel<<<dim3(Ln / QT, Hn, Bn), 256, attn_smem>>>(attn_bias);
    // 7) x1 = x + (attn @ proj_w^T + proj_b) * g1   -> d_out
    gemm_kernel<1><<<dim3(Cdim / BN, ROWS / BM), 256>>>(
        gattnP, proj_w, out, ROWS, Cdim, Cdim, proj_b, nullptr, x);
    // 8) h = LN(x1)*(s2+1)+sh2
    ln_mod_kernel<<<ROWS, 256>>>(out, ghP, 3, 5);
    // 9) ffn = gelu(h @ fc1_w^T + fc1_b)
    gemm_kernel<2><<<dim3(DFF / BN, ROWS / BM), 256>>>(
        ghP, fc1_w, gffnP, ROWS, DFF, Cdim, fc1_b, nullptr, nullptr);
    // 10) out += (ffn @ fc2_w^T + fc2_b) * g2
    gemm_kernel<3><<<dim3(Cdim / BN, ROWS / BM), 256>>>(
        gffnP, fc2_w, out, ROWS, Cdim, DFF, fc2_b, nullptr, nullptr);
}

// round 2
// speedup vs baseline: 3.9113x; 3.9113x over previous
#include <cuda_runtime.h>
#include <cuda_bf16.h>
#include <math.h>

// ---------------------------------------------------------------------------
// Problem constants
// ---------------------------------------------------------------------------
#define Cdim   1024
#define Hn     16
#define DH     64
#define DFF    4096
#define Ddim   1024
#define Bn     2
#define Ln     2048
#define ROWS   (Bn * Ln)          // 4096
#define MAX_SCALE_MUL 4.605170185988092f
#define LN_EPS 1e-6f
#define FULLM  0xFFFFFFFFu

// ---------------------------------------------------------------------------
// Scratch
// ---------------------------------------------------------------------------
__device__ float g_silu[Bn * Ddim];
__device__ float g_ada [Bn * 6 * Cdim];
__device__ float g_h   [ROWS * Cdim];
__device__ float g_qkv [ROWS * 3 * Cdim];
__device__ float g_attn[ROWS * Cdim];
__device__ float g_ffn [ROWS * DFF];

// ---------------------------------------------------------------------------
// Helpers
// ---------------------------------------------------------------------------
__device__ __forceinline__ float warp_sum(float v) {
    #pragma unroll
    for (int o = 16; o; o >>= 1) v += __shfl_xor_sync(FULLM, v, o);
    return v;
}
__device__ __forceinline__ float block_sum(float v, float* red) {
    __syncthreads();
    int lane = threadIdx.x & 31, w = threadIdx.x >> 5;
    v = warp_sum(v);
    if (lane == 0) red[w] = v;
    __syncthreads();
    if (w == 0) {
        float x = (lane < (int)(blockDim.x >> 5)) ? red[lane] : 0.f;
        x = warp_sum(x);
        if (lane == 0) red[0] = x;
    }
    __syncthreads();
    return red[0];
}
__device__ __forceinline__ unsigned f2tf(float f) {
    unsigned u;
    asm("cvt.rna.tf32.f32 %0, %1;" : "=r"(u) : "f"(f));
    return u;
}
__device__ __forceinline__ void mma_tf32(float c[4], const unsigned a[4], const unsigned b[2]) {
    asm("mma.sync.aligned.m16n8k8.row.col.f32.tf32.tf32.f32 "
        "{%0,%1,%2,%3}, {%4,%5,%6,%7}, {%8,%9}, {%0,%1,%2,%3};"
        : "+f"(c[0]), "+f"(c[1]), "+f"(c[2]), "+f"(c[3])
        : "r"(a[0]), "r"(a[1]), "r"(a[2]), "r"(a[3]), "r"(b[0]), "r"(b[1]));
}

// ---------------------------------------------------------------------------
// SiLU(cond)
// ---------------------------------------------------------------------------
__global__ void silu_kernel(const float* __restrict__ cond) {
    int i = blockIdx.x * blockDim.x + threadIdx.x;
    if (i < Bn * Ddim) {
        float v = cond[i];
        g_silu[i] = v / (1.f + expf(-v));
    }
}

// ---------------------------------------------------------------------------
// ada = silu(cond) @ ada_w^T + ada_b  (one warp per output element; tiny GEMV)
// ---------------------------------------------------------------------------
__global__ void ada_kernel(const float* __restrict__ ada_w,
                           const float* __restrict__ ada_b) {
    int gw   = (blockIdx.x * blockDim.x + threadIdx.x) >> 5;
    int lane = threadIdx.x & 31;
    if (gw >= Bn * 6 * Cdim) return;
    int b = gw / (6 * Cdim), j = gw % (6 * Cdim);
    const float* wv = ada_w + (size_t)j * Ddim;
    const float* sv = g_silu + b * Ddim;
    float acc = 0.f;
    #pragma unroll 2
    for (int i = lane * 4; i < Ddim; i += 128) {
        float4 w4 = *(const float4*)(wv + i);
        float4 s4 = *(const float4*)(sv + i);
        acc += w4.x * s4.x + w4.y * s4.y + w4.z * s4.z + w4.w * s4.w;
    }
    acc = warp_sum(acc);
    if (lane == 0) g_ada[b * 6 * Cdim + j] = acc + ada_b[j];
}

// ---------------------------------------------------------------------------
// h = LN(x) * (s+1) + sh
// ---------------------------------------------------------------------------
__global__ void ln_mod_kernel(const float* __restrict__ x, float* __restrict__ h,
                              int sChunk, int shChunk) {
    __shared__ float red[32];
    int row = blockIdx.x;
    int b   = row >> 11;
    const float* xr = x + (size_t)row * Cdim;
    int c = threadIdx.x * 4;
    float4 v = *(const float4*)(xr + c);
    float tot  = block_sum(v.x + v.y + v.z + v.w, red);
    float mean = tot * (1.f / Cdim);
    float dx = v.x - mean, dy = v.y - mean, dz = v.z - mean, dw = v.w - mean;
    float tss  = block_sum(dx * dx + dy * dy + dz * dz + dw * dw, red);
    float rstd = rsqrtf(tss * (1.f / Cdim) + LN_EPS);
    const float* sP  = g_ada + b * 6 * Cdim + sChunk  * Cdim;
    const float* shP = g_ada + b * 6 * Cdim + shChunk * Cdim;
    float4 s4  = *(const float4*)(sP  + c);
    float4 sh4 = *(const float4*)(shP + c);
    float4 o;
    o.x = dx * rstd * (s4.x + 1.f) + sh4.x;
    o.y = dy * rstd * (s4.y + 1.f) + sh4.y;
    o.z = dz * rstd * (s4.z + 1.f) + sh4.z;
    o.w = dw * rstd * (s4.w + 1.f) + sh4.w;
    *(float4*)(h + (size_t)row * Cdim + c) = o;
}

// ---------------------------------------------------------------------------
// TF32 tensor-core GEMM: C[M,N] = A[M,K] @ W[N,K]^T (+ fused epilogue)
//   MODE 0: QKV   MODE 1: PROJ   MODE 2: FC1+GELU   MODE 3: FC2 (in place)
// Block 128x128, BK=16, 8 warps as 4(M)x2(N), warp tile 32x64 (2x8 mma tiles)
// ---------------------------------------------------------------------------
template <int MODE>
__global__ __launch_bounds__(256, 2)
void gemm_tc(const float* __restrict__ A, const float* __restrict__ W,
             float* __restrict__ C, int M, int N, int K,
             const float* __restrict__ bias,
             const float* __restrict__ bias2,
             const float* __restrict__ res) {
    __shared__ unsigned As[128][20];   // row-major [m][k], pad 16->20
    __shared__ unsigned Ws[128][20];   // row-major [n][k]

    const int tid  = threadIdx.x;
    const int lane = tid & 31;
    const int warp = tid >> 5;
    const int wm   = (warp & 3) * 32;
    const int wn   = (warp >> 2) * 64;
    const int gid  = lane >> 2;        // 0..7
    const int tig  = lane & 3;         // 0..3
    const int m0 = blockIdx.y * 128, n0 = blockIdx.x * 128;

    float c[2][8][4];
    #pragma unroll
    for (int i = 0; i < 2; i++)
        #pragma unroll
        for (int j = 0; j < 8; j++)
            #pragma unroll
            for (int q = 0; q < 4; q++) c[i][j][q] = 0.f;

    const int sm_ = tid >> 2;            // 0..63 (+64 with r)
    const int sk4 = (tid & 3) << 2;

    for (int kt = 0; kt < K; kt += 16) {
        #pragma unroll
        for (int r = 0; r < 2; r++) {
            int m = sm_ + r * 64;
            float4 av = *(const float4*)(A + (size_t)(m0 + m) * K + kt + sk4);
            uint4 ua; ua.x = f2tf(av.x); ua.y = f2tf(av.y); ua.z = f2tf(av.z); ua.w = f2tf(av.w);
            *(uint4*)&As[m][sk4] = ua;
            float4 wv = *(const float4*)(W + (size_t)(n0 + m) * K + kt + sk4);
            uint4 uw; uw.x = f2tf(wv.x); uw.y = f2tf(wv.y); uw.z = f2tf(wv.z); uw.w = f2tf(wv.w);
            *(uint4*)&Ws[m][sk4] = uw;
        }
        __syncthreads();
        #pragma unroll
        for (int ks = 0; ks < 16; ks += 8) {
            unsigned a[2][4], b[8][2];
            #pragma unroll
            for (int mt = 0; mt < 2; mt++) {
                int r0 = wm + mt * 16 + gid;
                a[mt][0] = As[r0][ks + tig];
                a[mt][1] = As[r0 + 8][ks + tig];
                a[mt][2] = As[r0][ks + tig + 4];
                a[mt][3] = As[r0 + 8][ks + tig + 4];
            }
            #pragma unroll
            for (int nt = 0; nt < 8; nt++) {
                int nr = wn + nt * 8 + gid;
                b[nt][0] = Ws[nr][ks + tig];
                b[nt][1] = Ws[nr][ks + tig + 4];
            }
            #pragma unroll
            for (int mt = 0; mt < 2; mt++)
                #pragma unroll
                for (int nt = 0; nt < 8; nt++)
                    mma_tf32(c[mt][nt], a[mt], b[nt]);
        }
        __syncthreads();
    }

    const int b_idx = m0 >> 11;
    #pragma unroll
    for (int mt = 0; mt < 2; mt++) {
        #pragma unroll
        for (int half = 0; half < 2; half++) {
            int row = m0 + wm + mt * 16 + gid + half * 8;
            #pragma unroll
            for (int nt = 0; nt < 8; nt++) {
                int col = n0 + wn + nt * 8 + tig * 2;
                float v0 = c[mt][nt][half * 2];
                float v1 = c[mt][nt][half * 2 + 1];
                float* cp = C + (size_t)row * N + col;
                float2 o2;
                if (MODE == 0) {
                    float bb0 = (col < Cdim) ? bias[col]
                              : (col < 2 * Cdim) ? 0.f : bias2[col - 2 * Cdim];
                    int col1 = col + 1;
                    float bb1 = (col1 < Cdim) ? bias[col1]
                              : (col1 < 2 * Cdim) ? 0.f : bias2[col1 - 2 * Cdim];
                    o2.x = v0 + bb0; o2.y = v1 + bb1;
                } else if (MODE == 1) {
                    float gg0 = g_ada[b_idx * 6 * Cdim + col];
                    float gg1 = g_ada[b_idx * 6 * Cdim + col + 1];
                    const float* rp = res + (size_t)row * Cdim + col;
                    o2.x = rp[0] + (v0 + bias[col])     * gg0;
                    o2.y = rp[1] + (v1 + bias[col + 1]) * gg1;
                } else if (MODE == 2) {
                    float xg0 = v0 + bias[col];
                    float xg1 = v1 + bias[col + 1];
                    float t0 = tanhf(0.7978845608028654f * (xg0 + 0.044715f * xg0 * xg0 * xg0));
                    float t1 = tanhf(0.7978845608028654f * (xg1 + 0.044715f * xg1 * xg1 * xg1));
                    o2.x = 0.5f * xg0 * (1.f + t0);
                    o2.y = 0.5f * xg1 * (1.f + t1);
                } else {
                    float gg0 = g_ada[b_idx * 6 * Cdim + Cdim + col];
                    float gg1 = g_ada[b_idx * 6 * Cdim + Cdim + col + 1];
                    float2 cur = *(float2*)cp;
                    o2.x = cur.x + (v0 + bias[col])     * gg0;
                    o2.y = cur.y + (v1 + bias[col + 1]) * gg1;
                }
                *(float2*)cp = o2;
            }
        }
    }
}

// ---------------------------------------------------------------------------
// Normalize q,k per (row, head)
// ---------------------------------------------------------------------------
__global__ void norm_qk_kernel(const float* __restrict__ scale_mul) {
    int gw   = (blockIdx.x * blockDim.x + threadIdx.x) >> 5;
    int lane = threadIdx.x & 31;
    if (gw >= ROWS * Hn) return;
    int row = gw >> 4, h = gw & 15;
    float sm = expf(fminf(scale_mul[h], MAX_SCALE_MUL));
    float* q = g_qkv + (size_t)row * (3 * Cdim) + h * DH;
    float* k = q + Cdim;

    float2 qv = *(float2*)(q + lane * 2);
    float  sq = warp_sum(qv.x * qv.x + qv.y * qv.y);
    float  rq = rsqrtf(fmaxf(sq, 1e-24f)) * sm;
    qv.x *= rq; qv.y *= rq;
    *(float2*)(q + lane * 2) = qv;

    float2 kv = *(float2*)(k + lane * 2);
    float  sk = warp_sum(kv.x * kv.x + kv.y * kv.y);
    float  rk = rsqrtf(fmaxf(sk, 1e-24f));
    kv.x *= rk; kv.y *= rk;
    *(float2*)(k + lane * 2) = kv;
}

// ---------------------------------------------------------------------------
// Flash attention with tf32 MMA.
// Block: 128 q-rows x (h, b). 8 warps, each 16 q-rows. KV tiles of 64.
// smem (tf32 bits): Q[128][68], K[64][68], V[64][68]
// ---------------------------------------------------------------------------
#define AQT 128
#define AKT 64
#define ASTR 68

__global__ __launch_bounds__(256)
void attn_tc_kernel(const float* __restrict__ attn_bias) {
    extern __shared__ unsigned asm_[];
    unsigned* Qs = asm_;                    // 128*68
    unsigned* Ks = Qs + AQT * ASTR;         // 64*68
    unsigned* Vs = Ks + AKT * ASTR;         // 64*68

    const int tid  = threadIdx.x;
    const int lane = tid & 31;
    const int w    = tid >> 5;
    const int gid  = lane >> 2;
    const int tig  = lane & 3;
    const int qt = blockIdx.x, h = blockIdx.y, b = blockIdx.z;
    const int qbase = b * Ln + qt * AQT;

    // Stage Q (tf32)
    #pragma unroll
    for (int r = 0; r < 8; r++) {
        int idx = tid + r * 256;            // 0..2047
        int qr  = idx >> 4;
        int c4  = (idx & 15) << 2;
        float4 v = *(const float4*)(g_qkv + (size_t)(qbase + qr) * (3 * Cdim) + h * DH + c4);
        uint4 u; u.x = f2tf(v.x); u.y = f2tf(v.y); u.z = f2tf(v.z); u.w = f2tf(v.w);
        *(uint4*)&Qs[qr * ASTR + c4] = u;
    }
    __syncthreads();

    // Q fragments, register-resident for whole KV loop
    unsigned qf[8][4];
    {
        int r0 = w * 16 + gid;
        #pragma unroll
        for (int kc = 0; kc < 8; kc++) {
            qf[kc][0] = Qs[r0 * ASTR + kc * 8 + tig];
            qf[kc][1] = Qs[(r0 + 8) * ASTR + kc * 8 + tig];
            qf[kc][2] = Qs[r0 * ASTR + kc * 8 + tig + 4];
            qf[kc][3] = Qs[(r0 + 8) * ASTR + kc * 8 + tig + 4];
        }
    }

    float m0r = -1e30f, m1r = -1e30f, l0 = 0.f, l1 = 0.f;
    float o[8][4];
    #pragma unroll
    for (int nt = 0; nt < 8; nt++)
        #pragma unroll
        for (int i = 0; i < 4; i++) o[nt][i] = 0.f;

    const int gq0 = qt * AQT + w * 16 + gid;   // bias row (position in L)

    for (int it = 0; it < Ln / AKT; it++) {
        __syncthreads();
        int kbase = b * Ln + it * AKT;
        #pragma unroll
        for (int r = 0; r < 4; r++) {
            int idx = tid + r * 256;        // 0..1023
            int kr  = idx >> 4;
            int c4  = (idx & 15) << 2;
            size_t base = (size_t)(kbase + kr) * (3 * Cdim) + h * DH + c4;
            float4 kv = *(const float4*)(g_qkv + base + Cdim);
            float4 vv = *(const float4*)(g_qkv + base + 2 * Cdim);
            uint4 uk; uk.x = f2tf(kv.x); uk.y = f2tf(kv.y); uk.z = f2tf(kv.z); uk.w = f2tf(kv.w);
            uint4 uv; uv.x = f2tf(vv.x); uv.y = f2tf(vv.y); uv.z = f2tf(vv.z); uv.w = f2tf(vv.w);
            *(uint4*)&Ks[kr * ASTR + c4] = uk;
            *(uint4*)&Vs[kr * ASTR + c4] = uv;
        }
        __syncthreads();

        // S = Q K^T + bias
        float s[8][4];
        const float* bias0 = attn_bias + (size_t)gq0 * Ln + it * AKT;
        #pragma unroll
        for (int nt = 0; nt < 8; nt++) {
            #pragma unroll
            for (int i = 0; i < 4; i++) s[nt][i] = 0.f;
            #pragma unroll
            for (int kc = 0; kc < 8; kc++) {
                unsigned kb[2];
                int kvr = nt * 8 + gid;
                kb[0] = Ks[kvr * ASTR + kc * 8 + tig];
                kb[1] = Ks[kvr * ASTR + kc * 8 + tig + 4];
                mma_tf32(s[nt], qf[kc], kb);
            }
            float2 b0 = *(const float2*)(bias0 + nt * 8 + tig * 2);
            float2 b1 = *(const float2*)(bias0 + 8 * Ln + nt * 8 + tig * 2);
            s[nt][0] += b0.x; s[nt][1] += b0.y;
            s[nt][2] += b1.x; s[nt][3] += b1.y;
        }

        // online softmax
        float mx0 = -1e30f, mx1 = -1e30f;
        #pragma unroll
        for (int nt = 0; nt < 8; nt++) {
            mx0 = fmaxf(mx0, fmaxf(s[nt][0], s[nt][1]));
            mx1 = fmaxf(mx1, fmaxf(s[nt][2], s[nt][3]));
        }
        mx0 = fmaxf(mx0, __shfl_xor_sync(FULLM, mx0, 1));
        mx0 = fmaxf(mx0, __shfl_xor_sync(FULLM, mx0, 2));
        mx1 = fmaxf(mx1, __shfl_xor_sync(FULLM, mx1, 1));
        mx1 = fmaxf(mx1, __shfl_xor_sync(FULLM, mx1, 2));
        float nm0 = fmaxf(m0r, mx0), nm1 = fmaxf(m1r, mx1);
        float al0 = __expf(m0r - nm0), al1 = __expf(m1r - nm1);
        m0r = nm0; m1r = nm1;

        float sum0 = 0.f, sum1 = 0.f;
        #pragma unroll
        for (int nt = 0; nt < 8; nt++) {
            s[nt][0] = __expf(s[nt][0] - nm0);
            s[nt][1] = __expf(s[nt][1] - nm0);
            s[nt][2] = __expf(s[nt][2] - nm1);
            s[nt][3] = __expf(s[nt][3] - nm1);
            sum0 += s[nt][0] + s[nt][1];
            sum1 += s[nt][2] + s[nt][3];
        }
        sum0 += __shfl_xor_sync(FULLM, sum0, 1);
        sum0 += __shfl_xor_sync(FULLM, sum0, 2);
        sum1 += __shfl_xor_sync(FULLM, sum1, 1);
        sum1 += __shfl_xor_sync(FULLM, sum1, 2);
        l0 = l0 * al0 + sum0;
        l1 = l1 * al1 + sum1;
        #pragma unroll
        for (int nt = 0; nt < 8; nt++) {
            o[nt][0] *= al0; o[nt][1] *= al0;
            o[nt][2] *= al1; o[nt][3] *= al1;
        }

        // O += P V   (re-fragment P via shuffles)
        const int src1 = (lane & ~3) | (tig >> 1);
        const int src2 = src1 + 2;
        #pragma unroll
        for (int kc = 0; kc < 8; kc++) {
            float x0 = __shfl_sync(FULLM, s[kc][0], src1);
            float x1 = __shfl_sync(FULLM, s[kc][1], src1);
            float y0 = __shfl_sync(FULLM, s[kc][2], src1);
            float y1 = __shfl_sync(FULLM, s[kc][3], src1);
            float z0 = __shfl_sync(FULLM, s[kc][0], src2);
            float z1 = __shfl_sync(FULLM, s[kc][1], src2);
            float w0 = __shfl_sync(FULLM, s[kc][2], src2);
            float w1 = __shfl_sync(FULLM, s[kc][3], src2);
            unsigned pf[4];
            pf[0] = f2tf((tig & 1) ? x1 : x0);
            pf[1] = f2tf((tig & 1) ? y1 : y0);
            pf[2] = f2tf((tig & 1) ? z1 : z0);
            pf[3] = f2tf((tig & 1) ? w1 : w0);
            #pragma unroll
            for (int nt = 0; nt < 8; nt++) {
                unsigned vb[2];
                vb[0] = Vs[(kc * 8 + tig) * ASTR + nt * 8 + gid];
                vb[1] = Vs[(kc * 8 + tig + 4) * ASTR + nt * 8 + gid];
                mma_tf32(o[nt], pf, vb);
            }
        }
    }

    // write O / l
    float inv0 = 1.f / l0, inv1 = 1.f / l1;
    int row0 = qbase + w * 16 + gid;
    #pragma unroll
    for (int nt = 0; nt < 8; nt++) {
        int col = h * DH + nt * 8 + tig * 2;
        float2 o0; o0.x = o[nt][0] * inv0; o0.y = o[nt][1] * inv0;
        float2 o1; o1.x = o[nt][2] * inv1; o1.y = o[nt][3] * inv1;
        *(float2*)(g_attn + (size_t)row0 * Cdim + col)       = o0;
        *(float2*)(g_attn + (size_t)(row0 + 8) * Cdim + col) = o1;
    }
}

// ---------------------------------------------------------------------------
// Launch
// ---------------------------------------------------------------------------
extern "C" void kernel_launch(void* const* d_in, const int* in_sizes, int n_in,
                              void* d_out, int out_size) {
    const float* x         = (const float*)d_in[0];
    const float* cond      = (const float*)d_in[1];
    const float* attn_bias = (const float*)d_in[2];
    const float* qkv_w     = (const float*)d_in[3];
    const float* q_bias    = (const float*)d_in[4];
    const float* v_bias    = (const float*)d_in[5];
    const float* scale_mul = (const float*)d_in[6];
    const float* proj_w    = (const float*)d_in[7];
    const float* proj_b    = (const float*)d_in[8];
    const float* fc1_w     = (const float*)d_in[9];
    const float* fc1_b     = (const float*)d_in[10];
    const float* fc2_w     = (const float*)d_in[11];
    const float* fc2_b     = (const float*)d_in[12];
    const float* ada_w     = (const float*)d_in[13];
    const float* ada_b     = (const float*)d_in[14];
    float* out = (float*)d_out;

    float* gqkvP;  cudaGetSymbolAddress((void**)&gqkvP,  g_qkv);
    float* ghP;    cudaGetSymbolAddress((void**)&ghP,    g_h);
    float* gattnP; cudaGetSymbolAddress((void**)&gattnP, g_attn);
    float* gffnP;  cudaGetSymbolAddress((void**)&gffnP,  g_ffn);

    int attn_smem = (AQT + 2 * AKT) * ASTR * (int)sizeof(unsigned);  // 69632 B
    cudaFuncSetAttribute(attn_tc_kernel, cudaFuncAttributeMaxDynamicSharedMemorySize, attn_smem);

    // 1) SiLU(cond)
    silu_kernel<<<(Bn * Ddim + 255) / 256, 256>>>(cond);
    // 2) adaLN linear
    ada_kernel<<<(Bn * 6 * Cdim * 32 + 255) / 256, 256>>>(ada_w, ada_b);
    // 3) h = LN(x)*(s1+1)+sh1
    ln_mod_kernel<<<ROWS, 256>>>(x, ghP, 2, 4);
    // 4) qkv = h @ qkv_w^T + bias
    gemm_tc<0><<<dim3(3 * Cdim / 128, ROWS / 128), 256>>>(
        ghP, qkv_w, gqkvP, ROWS, 3 * Cdim, Cdim, q_bias, v_bias, nullptr);
    // 5) normalize q,k
    norm_qk_kernel<<<(ROWS * Hn * 32 + 255) / 256, 256>>>(scale_mul);
    // 6) attention
    attn_tc_kernel<<<dim3(Ln / AQT, Hn, Bn), 256, attn_smem>>>(attn_bias);
    // 7) x1 = x + (attn @ proj_w^T + proj_b) * g1
    gemm_tc<1><<<dim3(Cdim / 128, ROWS / 128), 256>>>(
        gattnP, proj_w, out, ROWS, Cdim, Cdim, proj_b, nullptr, x);
    // 8) h = LN(x1)*(s2+1)+sh2
    ln_mod_kernel<<<ROWS, 256>>>(out, ghP, 3, 5);
    // 9) ffn = gelu(h @ fc1_w^T + fc1_b)
    gemm_tc<2><<<dim3(DFF / 128, ROWS / 128), 256>>>(
        ghP, fc1_w, gffnP, ROWS, DFF, Cdim, fc1_b, nullptr, nullptr);
    // 10) out += (ffn @ fc2_w^T + fc2_b) * g2
    gemm_tc<3><<<dim3(Cdim / 128, ROWS / 128), 256>>>(
        gffnP, fc2_w, out, ROWS, Cdim, DFF, fc2_b, nullptr, nullptr);
}

// round 4
// speedup vs baseline: 4.8057x; 1.2287x over previous
#include <cuda_runtime.h>
#include <cuda_bf16.h>
#include <math.h>

// ---------------------------------------------------------------------------
// Problem constants
// ---------------------------------------------------------------------------
#define Cdim   1024
#define Hn     16
#define DH     64
#define DFF    4096
#define Ddim   1024
#define Bn     2
#define Ln     2048
#define ROWS   (Bn * Ln)          // 4096
#define MAX_SCALE_MUL 4.605170185988092f
#define LN_EPS 1e-6f
#define FULLM  0xFFFFFFFFu

// ---------------------------------------------------------------------------
// Scratch
// ---------------------------------------------------------------------------
__device__ float g_silu[Bn * Ddim];
__device__ float g_ada [Bn * 6 * Cdim];
__device__ float g_h   [ROWS * Cdim];
__device__ float g_qkv [ROWS * 3 * Cdim];
__device__ float g_attn[ROWS * Cdim];
__device__ float g_ffn [ROWS * DFF];

// ---------------------------------------------------------------------------
// Helpers
// ---------------------------------------------------------------------------
__device__ __forceinline__ float warp_sum(float v) {
    #pragma unroll
    for (int o = 16; o; o >>= 1) v += __shfl_xor_sync(FULLM, v, o);
    return v;
}
__device__ __forceinline__ float block_sum(float v, float* red) {
    __syncthreads();
    int lane = threadIdx.x & 31, w = threadIdx.x >> 5;
    v = warp_sum(v);
    if (lane == 0) red[w] = v;
    __syncthreads();
    if (w == 0) {
        float x = (lane < (int)(blockDim.x >> 5)) ? red[lane] : 0.f;
        x = warp_sum(x);
        if (lane == 0) red[0] = x;
    }
    __syncthreads();
    return red[0];
}
__device__ __forceinline__ void mma_tf32(float c[4], const unsigned a[4], const unsigned b[2]) {
    asm("mma.sync.aligned.m16n8k8.row.col.f32.tf32.tf32.f32 "
        "{%0,%1,%2,%3}, {%4,%5,%6,%7}, {%8,%9}, {%0,%1,%2,%3};"
        : "+f"(c[0]), "+f"(c[1]), "+f"(c[2]), "+f"(c[3])
        : "r"(a[0]), "r"(a[1]), "r"(a[2]), "r"(a[3]), "r"(b[0]), "r"(b[1]));
}
__device__ __forceinline__ void cp16(void* s, const void* g) {
    unsigned sa = (unsigned)__cvta_generic_to_shared(s);
    asm volatile("cp.async.cg.shared.global [%0], [%1], 16;\n" :: "r"(sa), "l"(g));
}
__device__ __forceinline__ void cp_commit() {
    asm volatile("cp.async.commit_group;\n");
}
template <int N> __device__ __forceinline__ void cp_wait() {
    asm volatile("cp.async.wait_group %0;\n" :: "n"(N));
}

// ---------------------------------------------------------------------------
// SiLU(cond)
// ---------------------------------------------------------------------------
__global__ void silu_kernel(const float* __restrict__ cond) {
    int i = blockIdx.x * blockDim.x + threadIdx.x;
    if (i < Bn * Ddim) {
        float v = cond[i];
        g_silu[i] = v / (1.f + expf(-v));
    }
}

// ---------------------------------------------------------------------------
// ada = silu(cond) @ ada_w^T + ada_b
// ---------------------------------------------------------------------------
__global__ void ada_kernel(const float* __restrict__ ada_w,
                           const float* __restrict__ ada_b) {
    int gw   = (blockIdx.x * blockDim.x + threadIdx.x) >> 5;
    int lane = threadIdx.x & 31;
    if (gw >= Bn * 6 * Cdim) return;
    int b = gw / (6 * Cdim), j = gw % (6 * Cdim);
    const float* wv = ada_w + (size_t)j * Ddim;
    const float* sv = g_silu + b * Ddim;
    float acc = 0.f;
    #pragma unroll 2
    for (int i = lane * 4; i < Ddim; i += 128) {
        float4 w4 = *(const float4*)(wv + i);
        float4 s4 = *(const float4*)(sv + i);
        acc += w4.x * s4.x + w4.y * s4.y + w4.z * s4.z + w4.w * s4.w;
    }
    acc = warp_sum(acc);
    if (lane == 0) g_ada[b * 6 * Cdim + j] = acc + ada_b[j];
}

// ---------------------------------------------------------------------------
// h = LN(x) * (s+1) + sh
// ---------------------------------------------------------------------------
__global__ void ln_mod_kernel(const float* __restrict__ x, float* __restrict__ h,
                              int sChunk, int shChunk) {
    __shared__ float red[32];
    int row = blockIdx.x;
    int b   = row >> 11;
    const float* xr = x + (size_t)row * Cdim;
    int c = threadIdx.x * 4;
    float4 v = *(const float4*)(xr + c);
    float tot  = block_sum(v.x + v.y + v.z + v.w, red);
    float mean = tot * (1.f / Cdim);
    float dx = v.x - mean, dy = v.y - mean, dz = v.z - mean, dw = v.w - mean;
    float tss  = block_sum(dx * dx + dy * dy + dz * dz + dw * dw, red);
    float rstd = rsqrtf(tss * (1.f / Cdim) + LN_EPS);
    const float* sP  = g_ada + b * 6 * Cdim + sChunk  * Cdim;
    const float* shP = g_ada + b * 6 * Cdim + shChunk * Cdim;
    float4 s4  = *(const float4*)(sP  + c);
    float4 sh4 = *(const float4*)(shP + c);
    float4 o;
    o.x = dx * rstd * (s4.x + 1.f) + sh4.x;
    o.y = dy * rstd * (s4.y + 1.f) + sh4.y;
    o.z = dz * rstd * (s4.z + 1.f) + sh4.z;
    o.w = dw * rstd * (s4.w + 1.f) + sh4.w;
    *(float4*)(h + (size_t)row * Cdim + c) = o;
}

// ---------------------------------------------------------------------------
// TF32 tensor-core GEMM, 3-stage cp.async pipeline.
// C[M,N] = A[M,K] @ W[N,K]^T (+ fused epilogue)
// Block 128x128, BK=16, 8 warps as 4(M)x2(N), warp tile 32x64.
// Raw fp32 bits fed to mma (HW truncates to tf32) — no cvt in staging path.
// ---------------------------------------------------------------------------
#define GSTAGES 3
#define GPAD 20
#define GTILE (128 * GPAD)

template <int MODE>
__global__ __launch_bounds__(256, 2)
void gemm_tc(const float* __restrict__ A, const float* __restrict__ W,
             float* __restrict__ C, int M, int N, int K,
             const float* __restrict__ bias,
             const float* __restrict__ bias2,
             const float* __restrict__ res) {
    extern __shared__ float gsm[];
    float* AsB = gsm;                       // [GSTAGES][128][GPAD]
    float* WsB = gsm + GSTAGES * GTILE;

    const int tid  = threadIdx.x;
    const int lane = tid & 31;
    const int warp = tid >> 5;
    const int wm   = (warp & 3) * 32;
    const int wn   = (warp >> 2) * 64;
    const int gid  = lane >> 2;
    const int tig  = lane & 3;
    const int m0 = blockIdx.y * 128, n0 = blockIdx.x * 128;

    const int sm_ = tid >> 2;               // 0..63
    const int sk4 = (tid & 3) << 2;

    float c[2][8][4];
    #pragma unroll
    for (int i = 0; i < 2; i++)
        #pragma unroll
        for (int j = 0; j < 8; j++)
            #pragma unroll
            for (int q = 0; q < 4; q++) c[i][j][q] = 0.f;

    const int ktotal = K >> 4;

    // ---- staging (cp.async 16B, raw fp32) ----
    auto stage = [&](int s, int slot) {
        float* As = AsB + slot * GTILE;
        float* Ws = WsB + slot * GTILE;
        int kt = s << 4;
        #pragma unroll
        for (int r = 0; r < 2; r++) {
            int m = sm_ + r * 64;
            cp16(&As[m * GPAD + sk4], A + (size_t)(m0 + m) * K + kt + sk4);
            cp16(&Ws[m * GPAD + sk4], W + (size_t)(n0 + m) * K + kt + sk4);
        }
    };

    stage(0, 0); cp_commit();
    stage(1, 1); cp_commit();
    cp_wait<1>();
    __syncthreads();

    for (int s = 0; s < ktotal; s++) {
        int nxt = s + 2;
        if (nxt < ktotal) stage(nxt, nxt % GSTAGES);
        cp_commit();

        const float* As = AsB + (s % GSTAGES) * GTILE;
        const float* Ws = WsB + (s % GSTAGES) * GTILE;
        #pragma unroll
        for (int ks = 0; ks < 16; ks += 8) {
            unsigned a[2][4], b[8][2];
            #pragma unroll
            for (int mt = 0; mt < 2; mt++) {
                int r0 = wm + mt * 16 + gid;
                a[mt][0] = __float_as_uint(As[r0 * GPAD + ks + tig]);
                a[mt][1] = __float_as_uint(As[(r0 + 8) * GPAD + ks + tig]);
                a[mt][2] = __float_as_uint(As[r0 * GPAD + ks + tig + 4]);
                a[mt][3] = __float_as_uint(As[(r0 + 8) * GPAD + ks + tig + 4]);
            }
            #pragma unroll
            for (int nt = 0; nt < 8; nt++) {
                int nr = wn + nt * 8 + gid;
                b[nt][0] = __float_as_uint(Ws[nr * GPAD + ks + tig]);
                b[nt][1] = __float_as_uint(Ws[nr * GPAD + ks + tig + 4]);
            }
            #pragma unroll
            for (int mt = 0; mt < 2; mt++)
                #pragma unroll
                for (int nt = 0; nt < 8; nt++)
                    mma_tf32(c[mt][nt], a[mt], b[nt]);
        }
        cp_wait<1>();
        __syncthreads();
    }

    const int b_idx = m0 >> 11;
    #pragma unroll
    for (int mt = 0; mt < 2; mt++) {
        #pragma unroll
        for (int half = 0; half < 2; half++) {
            int row = m0 + wm + mt * 16 + gid + half * 8;
            #pragma unroll
            for (int nt = 0; nt < 8; nt++) {
                int col = n0 + wn + nt * 8 + tig * 2;
                float v0 = c[mt][nt][half * 2];
                float v1 = c[mt][nt][half * 2 + 1];
                float* cp = C + (size_t)row * N + col;
                float2 o2;
                if (MODE == 0) {
                    float bb0 = (col < Cdim) ? bias[col]
                              : (col < 2 * Cdim) ? 0.f : bias2[col - 2 * Cdim];
                    int col1 = col + 1;
                    float bb1 = (col1 < Cdim) ? bias[col1]
                              : (col1 < 2 * Cdim) ? 0.f : bias2[col1 - 2 * Cdim];
                    o2.x = v0 + bb0; o2.y = v1 + bb1;
                } else if (MODE == 1) {
                    float gg0 = g_ada[b_idx * 6 * Cdim + col];
                    float gg1 = g_ada[b_idx * 6 * Cdim + col + 1];
                    const float* rp = res + (size_t)row * Cdim + col;
                    o2.x = rp[0] + (v0 + bias[col])     * gg0;
                    o2.y = rp[1] + (v1 + bias[col + 1]) * gg1;
                } else if (MODE == 2) {
                    float xg0 = v0 + bias[col];
                    float xg1 = v1 + bias[col + 1];
                    float t0 = tanhf(0.7978845608028654f * (xg0 + 0.044715f * xg0 * xg0 * xg0));
                    float t1 = tanhf(0.7978845608028654f * (xg1 + 0.044715f * xg1 * xg1 * xg1));
                    o2.x = 0.5f * xg0 * (1.f + t0);
                    o2.y = 0.5f * xg1 * (1.f + t1);
                } else {
                    float gg0 = g_ada[b_idx * 6 * Cdim + Cdim + col];
                    float gg1 = g_ada[b_idx * 6 * Cdim + Cdim + col + 1];
                    float2 cur = *(float2*)cp;
                    o2.x = cur.x + (v0 + bias[col])     * gg0;
                    o2.y = cur.y + (v1 + bias[col + 1]) * gg1;
                }
                *(float2*)cp = o2;
            }
        }
    }
}

// ---------------------------------------------------------------------------
// Normalize q,k per (row, head)
// ---------------------------------------------------------------------------
__global__ void norm_qk_kernel(const float* __restrict__ scale_mul) {
    int gw   = (blockIdx.x * blockDim.x + threadIdx.x) >> 5;
    int lane = threadIdx.x & 31;
    if (gw >= ROWS * Hn) return;
    int row = gw >> 4, h = gw & 15;
    float sm = expf(fminf(scale_mul[h], MAX_SCALE_MUL));
    float* q = g_qkv + (size_t)row * (3 * Cdim) + h * DH;
    float* k = q + Cdim;

    float2 qv = *(float2*)(q + lane * 2);
    float  sq = warp_sum(qv.x * qv.x + qv.y * qv.y);
    float  rq = rsqrtf(fmaxf(sq, 1e-24f)) * sm;
    qv.x *= rq; qv.y *= rq;
    *(float2*)(q + lane * 2) = qv;

    float2 kv = *(float2*)(k + lane * 2);
    float  sk = warp_sum(kv.x * kv.x + kv.y * kv.y);
    float  rk = rsqrtf(fmaxf(sk, 1e-24f));
    kv.x *= rk; kv.y *= rk;
    *(float2*)(k + lane * 2) = kv;
}

// ---------------------------------------------------------------------------
// Flash attention with tf32 MMA + double-buffered cp.async K/V.
// Block: 128 q-rows x (h, b). 8 warps, each 16 q-rows. KV tiles of 64.
// smem (fp32): Q[128][68], K[2][64][68], V[2][64][68]
// ---------------------------------------------------------------------------
#define AQT 128
#define AKT 64
#define ASTR 68
#define AKV (AKT * ASTR)

__global__ __launch_bounds__(256)
void attn_tc_kernel(const float* __restrict__ attn_bias) {
    extern __shared__ float afsm[];
    float* Qs  = afsm;                       // 128*68
    float* KsB = Qs + AQT * ASTR;            // 2 stages
    float* VsB = KsB + 2 * AKV;

    const int tid  = threadIdx.x;
    const int lane = tid & 31;
    const int w    = tid >> 5;
    const int gid  = lane >> 2;
    const int tig  = lane & 3;
    const int qt = blockIdx.x, h = blockIdx.y, b = blockIdx.z;
    const int qbase = b * Ln + qt * AQT;
    const int NTILES = Ln / AKT;

    auto stage_kv = [&](int it, int slot) {
        int kbase = b * Ln + it * AKT;
        float* Ks = KsB + slot * AKV;
        float* Vs = VsB + slot * AKV;
        #pragma unroll
        for (int r = 0; r < 4; r++) {
            int idx = tid + r * 256;
            int kr  = idx >> 4;
            int c4  = (idx & 15) << 2;
            size_t base = (size_t)(kbase + kr) * (3 * Cdim) + h * DH + c4;
            cp16(&Ks[kr * ASTR + c4], g_qkv + base + Cdim);
            cp16(&Vs[kr * ASTR + c4], g_qkv + base + 2 * Cdim);
        }
    };

    stage_kv(0, 0); cp_commit();

    // Stage Q (raw fp32)
    #pragma unroll
    for (int r = 0; r < 8; r++) {
        int idx = tid + r * 256;
        int qr  = idx >> 4;
        int c4  = (idx & 15) << 2;
        float4 v = *(const float4*)(g_qkv + (size_t)(qbase + qr) * (3 * Cdim) + h * DH + c4);
        *(float4*)&Qs[qr * ASTR + c4] = v;
    }
    __syncthreads();

    // Q fragments register-resident
    unsigned qf[8][4];
    {
        int r0 = w * 16 + gid;
        #pragma unroll
        for (int kc = 0; kc < 8; kc++) {
            qf[kc][0] = __float_as_uint(Qs[r0 * ASTR + kc * 8 + tig]);
            qf[kc][1] = __float_as_uint(Qs[(r0 + 8) * ASTR + kc * 8 + tig]);
            qf[kc][2] = __float_as_uint(Qs[r0 * ASTR + kc * 8 + tig + 4]);
            qf[kc][3] = __float_as_uint(Qs[(r0 + 8) * ASTR + kc * 8 + tig + 4]);
        }
    }

    float m0r = -1e30f, m1r = -1e30f, l0 = 0.f, l1 = 0.f;
    float o[8][4];
    #pragma unroll
    for (int nt = 0; nt < 8; nt++)
        #pragma unroll
        for (int i = 0; i < 4; i++) o[nt][i] = 0.f;

    const int gq0 = qt * AQT + w * 16 + gid;

    for (int it = 0; it < NTILES; it++) {
        if (it + 1 < NTILES) stage_kv(it + 1, (it + 1) & 1);
        cp_commit();
        cp_wait<1>();
        __syncthreads();

        const float* Ks = KsB + (it & 1) * AKV;
        const float* Vs = VsB + (it & 1) * AKV;

        // S = Q K^T + bias
        float s[8][4];
        const float* bias0 = attn_bias + (size_t)gq0 * Ln + it * AKT;
        #pragma unroll
        for (int nt = 0; nt < 8; nt++) {
            #pragma unroll
            for (int i = 0; i < 4; i++) s[nt][i] = 0.f;
            #pragma unroll
            for (int kc = 0; kc < 8; kc++) {
                unsigned kb[2];
                int kvr = nt * 8 + gid;
                kb[0] = __float_as_uint(Ks[kvr * ASTR + kc * 8 + tig]);
                kb[1] = __float_as_uint(Ks[kvr * ASTR + kc * 8 + tig + 4]);
                mma_tf32(s[nt], qf[kc], kb);
            }
            float2 b0 = *(const float2*)(bias0 + nt * 8 + tig * 2);
            float2 b1 = *(const float2*)(bias0 + 8 * Ln + nt * 8 + tig * 2);
            s[nt][0] += b0.x; s[nt][1] += b0.y;
            s[nt][2] += b1.x; s[nt][3] += b1.y;
        }

        // online softmax
        float mx0 = -1e30f, mx1 = -1e30f;
        #pragma unroll
        for (int nt = 0; nt < 8; nt++) {
            mx0 = fmaxf(mx0, fmaxf(s[nt][0], s[nt][1]));
            mx1 = fmaxf(mx1, fmaxf(s[nt][2], s[nt][3]));
        }
        mx0 = fmaxf(mx0, __shfl_xor_sync(FULLM, mx0, 1));
        mx0 = fmaxf(mx0, __shfl_xor_sync(FULLM, mx0, 2));
        mx1 = fmaxf(mx1, __shfl_xor_sync(FULLM, mx1, 1));
        mx1 = fmaxf(mx1, __shfl_xor_sync(FULLM, mx1, 2));
        float nm0 = fmaxf(m0r, mx0), nm1 = fmaxf(m1r, mx1);
        float al0 = __expf(m0r - nm0), al1 = __expf(m1r - nm1);
        m0r = nm0; m1r = nm1;

        float sum0 = 0.f, sum1 = 0.f;
        #pragma unroll
        for (int nt = 0; nt < 8; nt++) {
            s[nt][0] = __expf(s[nt][0] - nm0);
            s[nt][1] = __expf(s[nt][1] - nm0);
            s[nt][2] = __expf(s[nt][2] - nm1);
            s[nt][3] = __expf(s[nt][3] - nm1);
            sum0 += s[nt][0] + s[nt][1];
            sum1 += s[nt][2] + s[nt][3];
        }
        sum0 += __shfl_xor_sync(FULLM, sum0, 1);
        sum0 += __shfl_xor_sync(FULLM, sum0, 2);
        sum1 += __shfl_xor_sync(FULLM, sum1, 1);
        sum1 += __shfl_xor_sync(FULLM, sum1, 2);
        l0 = l0 * al0 + sum0;
        l1 = l1 * al1 + sum1;
        #pragma unroll
        for (int nt = 0; nt < 8; nt++) {
            o[nt][0] *= al0; o[nt][1] *= al0;
            o[nt][2] *= al1; o[nt][3] *= al1;
        }

        // O += P V
        const int src1 = (lane & ~3) | (tig >> 1);
        const int src2 = src1 + 2;
        #pragma unroll
        for (int kc = 0; kc < 8; kc++) {
            float x0 = __shfl_sync(FULLM, s[kc][0], src1);
            float x1 = __shfl_sync(FULLM, s[kc][1], src1);
            float y0 = __shfl_sync(FULLM, s[kc][2], src1);
            float y1 = __shfl_sync(FULLM, s[kc][3], src1);
            float z0 = __shfl_sync(FULLM, s[kc][0], src2);
            float z1 = __shfl_sync(FULLM, s[kc][1], src2);
            float w0 = __shfl_sync(FULLM, s[kc][2], src2);
            float w1 = __shfl_sync(FULLM, s[kc][3], src2);
            unsigned pf[4];
            pf[0] = __float_as_uint((tig & 1) ? x1 : x0);
            pf[1] = __float_as_uint((tig & 1) ? y1 : y0);
            pf[2] = __float_as_uint((tig & 1) ? z1 : z0);
            pf[3] = __float_as_uint((tig & 1) ? w1 : w0);
            #pragma unroll
            for (int nt = 0; nt < 8; nt++) {
                unsigned vb[2];
                vb[0] = __float_as_uint(Vs[(kc * 8 + tig) * ASTR + nt * 8 + gid]);
                vb[1] = __float_as_uint(Vs[(kc * 8 + tig + 4) * ASTR + nt * 8 + gid]);
                mma_tf32(o[nt], pf, vb);
            }
        }
        __syncthreads();
    }

    float inv0 = 1.f / l0, inv1 = 1.f / l1;
    int row0 = qbase + w * 16 + gid;
    #pragma unroll
    for (int nt = 0; nt < 8; nt++) {
        int col = h * DH + nt * 8 + tig * 2;
        float2 o0; o0.x = o[nt][0] * inv0; o0.y = o[nt][1] * inv0;
        float2 o1; o1.x = o[nt][2] * inv1; o1.y = o[nt][3] * inv1;
        *(float2*)(g_attn + (size_t)row0 * Cdim + col)       = o0;
        *(float2*)(g_attn + (size_t)(row0 + 8) * Cdim + col) = o1;
    }
}

// ---------------------------------------------------------------------------
// Launch
// ---------------------------------------------------------------------------
extern "C" void kernel_launch(void* const* d_in, const int* in_sizes, int n_in,
                              void* d_out, int out_size) {
    const float* x         = (const float*)d_in[0];
    const float* cond      = (const float*)d_in[1];
    const float* attn_bias = (const float*)d_in[2];
    const float* qkv_w     = (const float*)d_in[3];
    const float* q_bias    = (const float*)d_in[4];
    const float* v_bias    = (const float*)d_in[5];
    const float* scale_mul = (const float*)d_in[6];
    const float* proj_w    = (const float*)d_in[7];
    const float* proj_b    = (const float*)d_in[8];
    const float* fc1_w     = (const float*)d_in[9];
    const float* fc1_b     = (const float*)d_in[10];
    const float* fc2_w     = (const float*)d_in[11];
    const float* fc2_b     = (const float*)d_in[12];
    const float* ada_w     = (const float*)d_in[13];
    const float* ada_b     = (const float*)d_in[14];
    float* out = (float*)d_out;

    float* gqkvP;  cudaGetSymbolAddress((void**)&gqkvP,  g_qkv);
    float* ghP;    cudaGetSymbolAddress((void**)&ghP,    g_h);
    float* gattnP; cudaGetSymbolAddress((void**)&gattnP, g_attn);
    float* gffnP;  cudaGetSymbolAddress((void**)&gffnP,  g_ffn);

    int gemm_smem = 2 * GSTAGES * GTILE * (int)sizeof(float);       // 61440
    cudaFuncSetAttribute(gemm_tc<0>, cudaFuncAttributeMaxDynamicSharedMemorySize, gemm_smem);
    cudaFuncSetAttribute(gemm_tc<1>, cudaFuncAttributeMaxDynamicSharedMemorySize, gemm_smem);
    cudaFuncSetAttribute(gemm_tc<2>, cudaFuncAttributeMaxDynamicSharedMemorySize, gemm_smem);
    cudaFuncSetAttribute(gemm_tc<3>, cudaFuncAttributeMaxDynamicSharedMemorySize, gemm_smem);
    int attn_smem = (AQT * ASTR + 4 * AKV) * (int)sizeof(float);    // 104448
    cudaFuncSetAttribute(attn_tc_kernel, cudaFuncAttributeMaxDynamicSharedMemorySize, attn_smem);

    // 1) SiLU(cond)
    silu_kernel<<<(Bn * Ddim + 255) / 256, 256>>>(cond);
    // 2) adaLN linear
    ada_kernel<<<(Bn * 6 * Cdim * 32 + 255) / 256, 256>>>(ada_w, ada_b);
    // 3) h = LN(x)*(s1+1)+sh1
    ln_mod_kernel<<<ROWS, 256>>>(x, ghP, 2, 4);
    // 4) qkv = h @ qkv_w^T + bias
    gemm_tc<0><<<dim3(3 * Cdim / 128, ROWS / 128), 256, gemm_smem>>>(
        ghP, qkv_w, gqkvP, ROWS, 3 * Cdim, Cdim, q_bias, v_bias, nullptr);
    // 5) normalize q,k
    norm_qk_kernel<<<(ROWS * Hn * 32 + 255) / 256, 256>>>(scale_mul);
    // 6) attention
    attn_tc_kernel<<<dim3(Ln / AQT, Hn, Bn), 256, attn_smem>>>(attn_bias);
    // 7) x1 = x + (attn @ proj_w^T + proj_b) * g1
    gemm_tc<1><<<dim3(Cdim / 128, ROWS / 128), 256, gemm_smem>>>(
        gattnP, proj_w, out, ROWS, Cdim, Cdim, proj_b, nullptr, x);
    // 8) h = LN(x1)*(s2+1)+sh2
    ln_mod_kernel<<<ROWS, 256>>>(out, ghP, 3, 5);
    // 9) ffn = gelu(h @ fc1_w^T + fc1_b)
    gemm_tc<2><<<dim3(DFF / 128, ROWS / 128), 256, gemm_smem>>>(
        ghP, fc1_w, gffnP, ROWS, DFF, Cdim, fc1_b, nullptr, nullptr);
    // 10) out += (ffn @ fc2_w^T + fc2_b) * g2
    gemm_tc<3><<<dim3(Cdim / 128, ROWS / 128), 256, gemm_smem>>>(
        gffnP, fc2_w, out, ROWS, Cdim, DFF, fc2_b, nullptr, nullptr);
}

// round 6
// speedup vs baseline: 4.8264x; 1.0043x over previous
#include <cuda_runtime.h>
#include <cuda_bf16.h>
#include <math.h>
#include <stdint.h>

// ---------------------------------------------------------------------------
// Problem constants
// ---------------------------------------------------------------------------
#define Cdim   1024
#define Hn     16
#define DH     64
#define DFF    4096
#define Ddim   1024
#define Bn     2
#define Ln     2048
#define ROWS   (Bn * Ln)          // 4096
#define MAX_SCALE_MUL 4.605170185988092f
#define LN_EPS 1e-6f
#define FULLM  0xFFFFFFFFu

// ---------------------------------------------------------------------------
// Scratch
// ---------------------------------------------------------------------------
__device__ float g_silu[Bn * Ddim];
__device__ float g_ada [Bn * 6 * Cdim];
__device__ float g_h   [ROWS * Cdim];
__device__ float g_qkv [ROWS * 3 * Cdim];
__device__ float g_attn[ROWS * Cdim];
__device__ float g_ffn [ROWS * DFF];

// ---------------------------------------------------------------------------
// Helpers
// ---------------------------------------------------------------------------
__device__ __forceinline__ float warp_sum(float v) {
    #pragma unroll
    for (int o = 16; o; o >>= 1) v += __shfl_xor_sync(FULLM, v, o);
    return v;
}
__device__ __forceinline__ float block_sum(float v, float* red) {
    __syncthreads();
    int lane = threadIdx.x & 31, w = threadIdx.x >> 5;
    v = warp_sum(v);
    if (lane == 0) red[w] = v;
    __syncthreads();
    if (w == 0) {
        float x = (lane < (int)(blockDim.x >> 5)) ? red[lane] : 0.f;
        x = warp_sum(x);
        if (lane == 0) red[0] = x;
    }
    __syncthreads();
    return red[0];
}
__device__ __forceinline__ void mma_tf32(float c[4], const unsigned a[4], const unsigned b[2]) {
    asm("mma.sync.aligned.m16n8k8.row.col.f32.tf32.tf32.f32 "
        "{%0,%1,%2,%3}, {%4,%5,%6,%7}, {%8,%9}, {%0,%1,%2,%3};"
        : "+f"(c[0]), "+f"(c[1]), "+f"(c[2]), "+f"(c[3])
        : "r"(a[0]), "r"(a[1]), "r"(a[2]), "r"(a[3]), "r"(b[0]), "r"(b[1]));
}
__device__ __forceinline__ void cp16(void* s, const void* g) {
    unsigned sa = (unsigned)__cvta_generic_to_shared(s);
    asm volatile("cp.async.cg.shared.global [%0], [%1], 16;\n" :: "r"(sa), "l"(g));
}
__device__ __forceinline__ void cp_commit() {
    asm volatile("cp.async.commit_group;\n");
}
template <int N> __device__ __forceinline__ void cp_wait() {
    asm volatile("cp.async.wait_group %0;\n" :: "n"(N));
}

// ---------------------------------------------------------------------------
// SiLU(cond)
// ---------------------------------------------------------------------------
__global__ void silu_kernel(const float* __restrict__ cond) {
    int i = blockIdx.x * blockDim.x + threadIdx.x;
    if (i < Bn * Ddim) {
        float v = cond[i];
        g_silu[i] = v / (1.f + expf(-v));
    }
}

// ---------------------------------------------------------------------------
// ada = silu(cond) @ ada_w^T + ada_b
// ---------------------------------------------------------------------------
__global__ void ada_kernel(const float* __restrict__ ada_w,
                           const float* __restrict__ ada_b) {
    int gw   = (blockIdx.x * blockDim.x + threadIdx.x) >> 5;
    int lane = threadIdx.x & 31;
    if (gw >= Bn * 6 * Cdim) return;
    int b = gw / (6 * Cdim), j = gw % (6 * Cdim);
    const float* wv = ada_w + (size_t)j * Ddim;
    const float* sv = g_silu + b * Ddim;
    float acc = 0.f;
    #pragma unroll 2
    for (int i = lane * 4; i < Ddim; i += 128) {
        float4 w4 = *(const float4*)(wv + i);
        float4 s4 = *(const float4*)(sv + i);
        acc += w4.x * s4.x + w4.y * s4.y + w4.z * s4.z + w4.w * s4.w;
    }
    acc = warp_sum(acc);
    if (lane == 0) g_ada[b * 6 * Cdim + j] = acc + ada_b[j];
}

// ---------------------------------------------------------------------------
// h = LN(x) * (s+1) + sh
// ---------------------------------------------------------------------------
__global__ void ln_mod_kernel(const float* __restrict__ x, float* __restrict__ h,
                              int sChunk, int shChunk) {
    __shared__ float red[32];
    int row = blockIdx.x;
    int b   = row >> 11;
    const float* xr = x + (size_t)row * Cdim;
    int c = threadIdx.x * 4;
    float4 v = *(const float4*)(xr + c);
    float tot  = block_sum(v.x + v.y + v.z + v.w, red);
    float mean = tot * (1.f / Cdim);
    float dx = v.x - mean, dy = v.y - mean, dz = v.z - mean, dw = v.w - mean;
    float tss  = block_sum(dx * dx + dy * dy + dz * dz + dw * dw, red);
    float rstd = rsqrtf(tss * (1.f / Cdim) + LN_EPS);
    const float* sP  = g_ada + b * 6 * Cdim + sChunk  * Cdim;
    const float* shP = g_ada + b * 6 * Cdim + shChunk * Cdim;
    float4 s4  = *(const float4*)(sP  + c);
    float4 sh4 = *(const float4*)(shP + c);
    float4 o;
    o.x = dx * rstd * (s4.x + 1.f) + sh4.x;
    o.y = dy * rstd * (s4.y + 1.f) + sh4.y;
    o.z = dz * rstd * (s4.z + 1.f) + sh4.z;
    o.w = dw * rstd * (s4.w + 1.f) + sh4.w;
    *(float4*)(h + (size_t)row * Cdim + c) = o;
}

// ---------------------------------------------------------------------------
// TF32 tensor-core GEMM, 3-stage cp.async pipeline, 64x64 warp tiles.
// C[M,N] = A[M,K] @ W[N,K]^T (+ fused epilogue)
// Block 128x128, BK=16, 4 warps as 2(M)x2(N), warp tile 64x64 (4x8 mma tiles).
// Fragment-LDS per block-ktile: A dup x2 + B dup x2 = 32KB (vs 48KB w/ 32x64).
//   MODE 0: QKV   MODE 1: PROJ   MODE 2: FC1+GELU   MODE 3: FC2 (in place)
// ---------------------------------------------------------------------------
#define GSTAGES 3
#define GPAD 20
#define GTILE (128 * GPAD)

template <int MODE>
__global__ __launch_bounds__(128, 2)
void gemm_tc(const float* __restrict__ A, const float* __restrict__ W,
             float* __restrict__ C, int M, int N, int K,
             const float* __restrict__ bias,
             const float* __restrict__ bias2,
             const float* __restrict__ res) {
    extern __shared__ float gsm[];
    float* AsB = gsm;                       // [GSTAGES][128][GPAD]
    float* WsB = gsm + GSTAGES * GTILE;

    const int tid  = threadIdx.x;
    const int lane = tid & 31;
    const int warp = tid >> 5;              // 0..3
    const int wm   = (warp & 1) * 64;
    const int wn   = (warp >> 1) * 64;
    const int gid  = lane >> 2;
    const int tig  = lane & 3;
    const int m0 = blockIdx.y * 128, n0 = blockIdx.x * 128;

    float c[4][8][4];
    #pragma unroll
    for (int i = 0; i < 4; i++)
        #pragma unroll
        for (int j = 0; j < 8; j++)
            #pragma unroll
            for (int q = 0; q < 4; q++) c[i][j][q] = 0.f;

    const int ktotal = K >> 4;

    // staging: 128 rows x 16 floats = 512 16B-chunks each for A and W; 128 thr -> 4 each
    auto stage = [&](int s, int slot) {
        float* As = AsB + slot * GTILE;
        float* Ws = WsB + slot * GTILE;
        int kt = s << 4;
        #pragma unroll
        for (int i = 0; i < 4; i++) {
            int idx = tid + i * 128;        // 0..511
            int row = idx >> 2;             // 0..127
            int ch  = (idx & 3) << 2;       // 0,4,8,12
            cp16(&As[row * GPAD + ch], A + (size_t)(m0 + row) * K + kt + ch);
            cp16(&Ws[row * GPAD + ch], W + (size_t)(n0 + row) * K + kt + ch);
        }
    };

    stage(0, 0); cp_commit();
    stage(1, 1); cp_commit();
    cp_wait<1>();
    __syncthreads();

    for (int s = 0; s < ktotal; s++) {
        int nxt = s + 2;
        if (nxt < ktotal) stage(nxt, nxt % GSTAGES);
        cp_commit();

        const float* As = AsB + (s % GSTAGES) * GTILE;
        const float* Ws = WsB + (s % GSTAGES) * GTILE;
        #pragma unroll
        for (int ks = 0; ks < 16; ks += 8) {
            unsigned a[4][4], b[8][2];
            #pragma unroll
            for (int mt = 0; mt < 4; mt++) {
                int r0 = wm + mt * 16 + gid;
                a[mt][0] = __float_as_uint(As[r0 * GPAD + ks + tig]);
                a[mt][1] = __float_as_uint(As[(r0 + 8) * GPAD + ks + tig]);
                a[mt][2] = __float_as_uint(As[r0 * GPAD + ks + tig + 4]);
                a[mt][3] = __float_as_uint(As[(r0 + 8) * GPAD + ks + tig + 4]);
            }
            #pragma unroll
            for (int nt = 0; nt < 8; nt++) {
                int nr = wn + nt * 8 + gid;
                b[nt][0] = __float_as_uint(Ws[nr * GPAD + ks + tig]);
                b[nt][1] = __float_as_uint(Ws[nr * GPAD + ks + tig + 4]);
            }
            #pragma unroll
            for (int mt = 0; mt < 4; mt++)
                #pragma unroll
                for (int nt = 0; nt < 8; nt++)
                    mma_tf32(c[mt][nt], a[mt], b[nt]);
        }
        cp_wait<1>();
        __syncthreads();
    }

    const int b_idx = m0 >> 11;
    #pragma unroll
    for (int mt = 0; mt < 4; mt++) {
        #pragma unroll
        for (int half = 0; half < 2; half++) {
            int row = m0 + wm + mt * 16 + gid + half * 8;
            #pragma unroll
            for (int nt = 0; nt < 8; nt++) {
                int col = n0 + wn + nt * 8 + tig * 2;
                float v0 = c[mt][nt][half * 2];
                float v1 = c[mt][nt][half * 2 + 1];
                float* cp = C + (size_t)row * N + col;
                float2 o2;
                if (MODE == 0) {
                    float bb0 = (col < Cdim) ? bias[col]
                              : (col < 2 * Cdim) ? 0.f : bias2[col - 2 * Cdim];
                    int col1 = col + 1;
                    float bb1 = (col1 < Cdim) ? bias[col1]
                              : (col1 < 2 * Cdim) ? 0.f : bias2[col1 - 2 * Cdim];
                    o2.x = v0 + bb0; o2.y = v1 + bb1;
                } else if (MODE == 1) {
                    float gg0 = g_ada[b_idx * 6 * Cdim + col];
                    float gg1 = g_ada[b_idx * 6 * Cdim + col + 1];
                    const float* rp = res + (size_t)row * Cdim + col;
                    o2.x = rp[0] + (v0 + bias[col])     * gg0;
                    o2.y = rp[1] + (v1 + bias[col + 1]) * gg1;
                } else if (MODE == 2) {
                    float xg0 = v0 + bias[col];
                    float xg1 = v1 + bias[col + 1];
                    float t0 = tanhf(0.7978845608028654f * (xg0 + 0.044715f * xg0 * xg0 * xg0));
                    float t1 = tanhf(0.7978845608028654f * (xg1 + 0.044715f * xg1 * xg1 * xg1));
                    o2.x = 0.5f * xg0 * (1.f + t0);
                    o2.y = 0.5f * xg1 * (1.f + t1);
                } else {
                    float gg0 = g_ada[b_idx * 6 * Cdim + Cdim + col];
                    float gg1 = g_ada[b_idx * 6 * Cdim + Cdim + col + 1];
                    float2 cur = *(float2*)cp;
                    o2.x = cur.x + (v0 + bias[col])     * gg0;
                    o2.y = cur.y + (v1 + bias[col + 1]) * gg1;
                }
                *(float2*)cp = o2;
            }
        }
    }
}

// ---------------------------------------------------------------------------
// Normalize q,k per (row, head)
// ---------------------------------------------------------------------------
__global__ void norm_qk_kernel(const float* __restrict__ scale_mul) {
    int gw   = (blockIdx.x * blockDim.x + threadIdx.x) >> 5;
    int lane = threadIdx.x & 31;
    if (gw >= ROWS * Hn) return;
    int row = gw >> 4, h = gw & 15;
    float sm = expf(fminf(scale_mul[h], MAX_SCALE_MUL));
    float* q = g_qkv + (size_t)row * (3 * Cdim) + h * DH;
    float* k = q + Cdim;

    float2 qv = *(float2*)(q + lane * 2);
    float  sq = warp_sum(qv.x * qv.x + qv.y * qv.y);
    float  rq = rsqrtf(fmaxf(sq, 1e-24f)) * sm;
    qv.x *= rq; qv.y *= rq;
    *(float2*)(q + lane * 2) = qv;

    float2 kv = *(float2*)(k + lane * 2);
    float  sk = warp_sum(kv.x * kv.x + kv.y * kv.y);
    float  rk = rsqrtf(fmaxf(sk, 1e-24f));
    kv.x *= rk; kv.y *= rk;
    *(float2*)(k + lane * 2) = kv;
}

// ---------------------------------------------------------------------------
// Flash attention with tf32 MMA + double-buffered cp.async K/V.
// Block: 128 q-rows x (h, b). 8 warps, each 16 q-rows. KV tiles of 64.
// ---------------------------------------------------------------------------
#define AQT 128
#define AKT 64
#define ASTR 68
#define AKV (AKT * ASTR)

__global__ __launch_bounds__(256)
void attn_tc_kernel(const float* __restrict__ attn_bias) {
    extern __shared__ float afsm[];
    float* Qs  = afsm;
    float* KsB = Qs + AQT * ASTR;
    float* VsB = KsB + 2 * AKV;

    const int tid  = threadIdx.x;
    const int lane = tid & 31;
    const int w    = tid >> 5;
    const int gid  = lane >> 2;
    const int tig  = lane & 3;
    const int qt = blockIdx.x, h = blockIdx.y, b = blockIdx.z;
    const int qbase = b * Ln + qt * AQT;
    const int NTILES = Ln / AKT;

    auto stage_kv = [&](int it, int slot) {
        int kbase = b * Ln + it * AKT;
        float* Ks = KsB + slot * AKV;
        float* Vs = VsB + slot * AKV;
        #pragma unroll
        for (int r = 0; r < 4; r++) {
            int idx = tid + r * 256;
            int kr  = idx >> 4;
            int c4  = (idx & 15) << 2;
            size_t base = (size_t)(kbase + kr) * (3 * Cdim) + h * DH + c4;
            cp16(&Ks[kr * ASTR + c4], g_qkv + base + Cdim);
            cp16(&Vs[kr * ASTR + c4], g_qkv + base + 2 * Cdim);
        }
    };

    stage_kv(0, 0); cp_commit();

    #pragma unroll
    for (int r = 0; r < 8; r++) {
        int idx = tid + r * 256;
        int qr  = idx >> 4;
        int c4  = (idx & 15) << 2;
        float4 v = *(const float4*)(g_qkv + (size_t)(qbase + qr) * (3 * Cdim) + h * DH + c4);
        *(float4*)&Qs[qr * ASTR + c4] = v;
    }
    __syncthreads();

    unsigned qf[8][4];
    {
        int r0 = w * 16 + gid;
        #pragma unroll
        for (int kc = 0; kc < 8; kc++) {
            qf[kc][0] = __float_as_uint(Qs[r0 * ASTR + kc * 8 + tig]);
            qf[kc][1] = __float_as_uint(Qs[(r0 + 8) * ASTR + kc * 8 + tig]);
            qf[kc][2] = __float_as_uint(Qs[r0 * ASTR + kc * 8 + tig + 4]);
            qf[kc][3] = __float_as_uint(Qs[(r0 + 8) * ASTR + kc * 8 + tig + 4]);
        }
    }

    float m0r = -1e30f, m1r = -1e30f, l0 = 0.f, l1 = 0.f;
    float o[8][4];
    #pragma unroll
    for (int nt = 0; nt < 8; nt++)
        #pragma unroll
        for (int i = 0; i < 4; i++) o[nt][i] = 0.f;

    const int gq0 = qt * AQT + w * 16 + gid;

    for (int it = 0; it < NTILES; it++) {
        if (it + 1 < NTILES) stage_kv(it + 1, (it + 1) & 1);
        cp_commit();
        cp_wait<1>();
        __syncthreads();

        const float* Ks = KsB + (it & 1) * AKV;
        const float* Vs = VsB + (it & 1) * AKV;

        float s[8][4];
        const float* bias0 = attn_bias + (size_t)gq0 * Ln + it * AKT;
        #pragma unroll
        for (int nt = 0; nt < 8; nt++) {
            #pragma unroll
            for (int i = 0; i < 4; i++) s[nt][i] = 0.f;
            #pragma unroll
            for (int kc = 0; kc < 8; kc++) {
                unsigned kb[2];
                int kvr = nt * 8 + gid;
                kb[0] = __float_as_uint(Ks[kvr * ASTR + kc * 8 + tig]);
                kb[1] = __float_as_uint(Ks[kvr * ASTR + kc * 8 + tig + 4]);
                mma_tf32(s[nt], qf[kc], kb);
            }
            float2 b0 = *(const float2*)(bias0 + nt * 8 + tig * 2);
            float2 b1 = *(const float2*)(bias0 + 8 * Ln + nt * 8 + tig * 2);
            s[nt][0] += b0.x; s[nt][1] += b0.y;
            s[nt][2] += b1.x; s[nt][3] += b1.y;
        }

        float mx0 = -1e30f, mx1 = -1e30f;
        #pragma unroll
        for (int nt = 0; nt < 8; nt++) {
            mx0 = fmaxf(mx0, fmaxf(s[nt][0], s[nt][1]));
            mx1 = fmaxf(mx1, fmaxf(s[nt][2], s[nt][3]));
        }
        mx0 = fmaxf(mx0, __shfl_xor_sync(FULLM, mx0, 1));
        mx0 = fmaxf(mx0, __shfl_xor_sync(FULLM, mx0, 2));
        mx1 = fmaxf(mx1, __shfl_xor_sync(FULLM, mx1, 1));
        mx1 = fmaxf(mx1, __shfl_xor_sync(FULLM, mx1, 2));
        float nm0 = fmaxf(m0r, mx0), nm1 = fmaxf(m1r, mx1);
        float al0 = __expf(m0r - nm0), al1 = __expf(m1r - nm1);
        m0r = nm0; m1r = nm1;

        float sum0 = 0.f, sum1 = 0.f;
        #pragma unroll
        for (int nt = 0; nt < 8; nt++) {
            s[nt][0] = __expf(s[nt][0] - nm0);
            s[nt][1] = __expf(s[nt][1] - nm0);
            s[nt][2] = __expf(s[nt][2] - nm1);
            s[nt][3] = __expf(s[nt][3] - nm1);
            sum0 += s[nt][0] + s[nt][1];
            sum1 += s[nt][2] + s[nt][3];
        }
        sum0 += __shfl_xor_sync(FULLM, sum0, 1);
        sum0 += __shfl_xor_sync(FULLM, sum0, 2);
        sum1 += __shfl_xor_sync(FULLM, sum1, 1);
        sum1 += __shfl_xor_sync(FULLM, sum1, 2);
        l0 = l0 * al0 + sum0;
        l1 = l1 * al1 + sum1;
        #pragma unroll
        for (int nt = 0; nt < 8; nt++) {
            o[nt][0] *= al0; o[nt][1] *= al0;
            o[nt][2] *= al1; o[nt][3] *= al1;
        }

        const int src1 = (lane & ~3) | (tig >> 1);
        const int src2 = src1 + 2;
        #pragma unroll
        for (int kc = 0; kc < 8; kc++) {
            float x0 = __shfl_sync(FULLM, s[kc][0], src1);
            float x1 = __shfl_sync(FULLM, s[kc][1], src1);
            float y0 = __shfl_sync(FULLM, s[kc][2], src1);
            float y1 = __shfl_sync(FULLM, s[kc][3], src1);
            float z0 = __shfl_sync(FULLM, s[kc][0], src2);
            float z1 = __shfl_sync(FULLM, s[kc][1], src2);
            float w0 = __shfl_sync(FULLM, s[kc][2], src2);
            float w1 = __shfl_sync(FULLM, s[kc][3], src2);
            unsigned pf[4];
            pf[0] = __float_as_uint((tig & 1) ? x1 : x0);
            pf[1] = __float_as_uint((tig & 1) ? y1 : y0);
            pf[2] = __float_as_uint((tig & 1) ? z1 : z0);
            pf[3] = __float_as_uint((tig & 1) ? w1 : w0);
            #pragma unroll
            for (int nt = 0; nt < 8; nt++) {
                unsigned vb[2];
                vb[0] = __float_as_uint(Vs[(kc * 8 + tig) * ASTR + nt * 8 + gid]);
                vb[1] = __float_as_uint(Vs[(kc * 8 + tig + 4) * ASTR + nt * 8 + gid]);
                mma_tf32(o[nt], pf, vb);
            }
        }
        __syncthreads();
    }

    float inv0 = 1.f / l0, inv1 = 1.f / l1;
    int row0 = qbase + w * 16 + gid;
    #pragma unroll
    for (int nt = 0; nt < 8; nt++) {
        int col = h * DH + nt * 8 + tig * 2;
        float2 o0; o0.x = o[nt][0] * inv0; o0.y = o[nt][1] * inv0;
        float2 o1; o1.x = o[nt][2] * inv1; o1.y = o[nt][3] * inv1;
        *(float2*)(g_attn + (size_t)row0 * Cdim + col)       = o0;
        *(float2*)(g_attn + (size_t)(row0 + 8) * Cdim + col) = o1;
    }
}

// ---------------------------------------------------------------------------
// Launch
// ---------------------------------------------------------------------------
extern "C" void kernel_launch(void* const* d_in, const int* in_sizes, int n_in,
                              void* d_out, int out_size) {
    const float* x         = (const float*)d_in[0];
    const float* cond      = (const float*)d_in[1];
    const float* attn_bias = (const float*)d_in[2];
    const float* qkv_w     = (const float*)d_in[3];
    const float* q_bias    = (const float*)d_in[4];
    const float* v_bias    = (const float*)d_in[5];
    const float* scale_mul = (const float*)d_in[6];
    const float* proj_w    = (const float*)d_in[7];
    const float* proj_b    = (const float*)d_in[8];
    const float* fc1_w     = (const float*)d_in[9];
    const float* fc1_b     = (const float*)d_in[10];
    const float* fc2_w     = (const float*)d_in[11];
    const float* fc2_b     = (const float*)d_in[12];
    const float* ada_w     = (const float*)d_in[13];
    const float* ada_b     = (const float*)d_in[14];
    float* out = (float*)d_out;

    float* gqkvP;  cudaGetSymbolAddress((void**)&gqkvP,  g_qkv);
    float* ghP;    cudaGetSymbolAddress((void**)&ghP,    g_h);
    float* gattnP; cudaGetSymbolAddress((void**)&gattnP, g_attn);
    float* gffnP;  cudaGetSymbolAddress((void**)&gffnP,  g_ffn);

    int gemm_smem = 2 * GSTAGES * GTILE * (int)sizeof(float);       // 61440
    cudaFuncSetAttribute(gemm_tc<0>, cudaFuncAttributeMaxDynamicSharedMemorySize, gemm_smem);
    cudaFuncSetAttribute(gemm_tc<1>, cudaFuncAttributeMaxDynamicSharedMemorySize, gemm_smem);
    cudaFuncSetAttribute(gemm_tc<2>, cudaFuncAttributeMaxDynamicSharedMemorySize, gemm_smem);
    cudaFuncSetAttribute(gemm_tc<3>, cudaFuncAttributeMaxDynamicSharedMemorySize, gemm_smem);
    int attn_smem = (AQT * ASTR + 4 * AKV) * (int)sizeof(float);    // 104448
    cudaFuncSetAttribute(attn_tc_kernel, cudaFuncAttributeMaxDynamicSharedMemorySize, attn_smem);

    // 1) SiLU(cond)
    silu_kernel<<<(Bn * Ddim + 255) / 256, 256>>>(cond);
    // 2) adaLN linear
    ada_kernel<<<(Bn * 6 * Cdim * 32 + 255) / 256, 256>>>(ada_w, ada_b);
    // 3) h = LN(x)*(s1+1)+sh1
    ln_mod_kernel<<<ROWS, 256>>>(x, ghP, 2, 4);
    // 4) qkv = h @ qkv_w^T + bias
    gemm_tc<0><<<dim3(3 * Cdim / 128, ROWS / 128), 128, gemm_smem>>>(
        ghP, qkv_w, gqkvP, ROWS, 3 * Cdim, Cdim, q_bias, v_bias, nullptr);
    // 5) normalize q,k
    norm_qk_kernel<<<(ROWS * Hn * 32 + 255) / 256, 256>>>(scale_mul);
    // 6) attention
    attn_tc_kernel<<<dim3(Ln / AQT, Hn, Bn), 256, attn_smem>>>(attn_bias);
    // 7) x1 = x + (attn @ proj_w^T + proj_b) * g1
    gemm_tc<1><<<dim3(Cdim / 128, ROWS / 128), 128, gemm_smem>>>(
        gattnP, proj_w, out, ROWS, Cdim, Cdim, proj_b, nullptr, x);
    // 8) h = LN(x1)*(s2+1)+sh2
    ln_mod_kernel<<<ROWS, 256>>>(out, ghP, 3, 5);
    // 9) ffn = gelu(h @ fc1_w^T + fc1_b)
    gemm_tc<2><<<dim3(DFF / 128, ROWS / 128), 128, gemm_smem>>>(
        ghP, fc1_w, gffnP, ROWS, DFF, Cdim, fc1_b, nullptr, nullptr);
    // 10) out += (ffn @ fc2_w^T + fc2_b) * g2
    gemm_tc<3><<<dim3(Cdim / 128, ROWS / 128), 128, gemm_smem>>>(
        gffnP, fc2_w, out, ROWS, Cdim, DFF, fc2_b, nullptr, nullptr);
}

// round 8
// speedup vs baseline: 10.1016x; 2.0930x over previous
#include <cuda_runtime.h>
#include <cuda_fp16.h>
#include <math.h>
#include <stdint.h>

// ---------------------------------------------------------------------------
// Problem constants
// ---------------------------------------------------------------------------
#define Cdim   1024
#define Hn     16
#define DH     64
#define DFF    4096
#define Ddim   1024
#define Bn     2
#define Ln     2048
#define ROWS   (Bn * Ln)          // 4096
#define MAX_SCALE_MUL 4.605170185988092f
#define LN_EPS 1e-6f
#define FULLM  0xFFFFFFFFu

// ---------------------------------------------------------------------------
// Scratch
// ---------------------------------------------------------------------------
__device__ float  g_silu[Bn * Ddim];
__device__ float  g_ada [Bn * 6 * Cdim];
__device__ __half g_h   [ROWS * Cdim];
__device__ __half g_qkv [ROWS * 3 * Cdim];
__device__ __half g_attn[ROWS * Cdim];
__device__ __half g_ffn [ROWS * DFF];
// half weights
__device__ __half g_wqkv[3 * Cdim * Cdim];
__device__ __half g_wproj[Cdim * Cdim];
__device__ __half g_wfc1[DFF * Cdim];
__device__ __half g_wfc2[Cdim * DFF];

// ---------------------------------------------------------------------------
// Helpers
// ---------------------------------------------------------------------------
__device__ __forceinline__ float warp_sum(float v) {
    #pragma unroll
    for (int o = 16; o; o >>= 1) v += __shfl_xor_sync(FULLM, v, o);
    return v;
}
__device__ __forceinline__ float block_sum(float v, float* red) {
    __syncthreads();
    int lane = threadIdx.x & 31, w = threadIdx.x >> 5;
    v = warp_sum(v);
    if (lane == 0) red[w] = v;
    __syncthreads();
    if (w == 0) {
        float x = (lane < (int)(blockDim.x >> 5)) ? red[lane] : 0.f;
        x = warp_sum(x);
        if (lane == 0) red[0] = x;
    }
    __syncthreads();
    return red[0];
}
__device__ __forceinline__ void mma_f16(float c[4], const unsigned a[4],
                                        unsigned b0, unsigned b1) {
    asm("mma.sync.aligned.m16n8k16.row.col.f32.f16.f16.f32 "
        "{%0,%1,%2,%3}, {%4,%5,%6,%7}, {%8,%9}, {%0,%1,%2,%3};"
        : "+f"(c[0]), "+f"(c[1]), "+f"(c[2]), "+f"(c[3])
        : "r"(a[0]), "r"(a[1]), "r"(a[2]), "r"(a[3]), "r"(b0), "r"(b1));
}
__device__ __forceinline__ void ldm4(unsigned r[4], uint32_t a) {
    asm volatile("ldmatrix.sync.aligned.m8n8.x4.shared.b16 {%0,%1,%2,%3}, [%4];"
        : "=r"(r[0]), "=r"(r[1]), "=r"(r[2]), "=r"(r[3]) : "r"(a));
}
__device__ __forceinline__ void ldm4t(unsigned r[4], uint32_t a) {
    asm volatile("ldmatrix.sync.aligned.m8n8.x4.trans.shared.b16 {%0,%1,%2,%3}, [%4];"
        : "=r"(r[0]), "=r"(r[1]), "=r"(r[2]), "=r"(r[3]) : "r"(a));
}
__device__ __forceinline__ unsigned packh2(float x, float y) {
    __half2 h = __floats2half2_rn(x, y);
    return *(unsigned*)&h;
}
__device__ __forceinline__ void cp16(void* s, const void* g) {
    unsigned sa = (unsigned)__cvta_generic_to_shared(s);
    asm volatile("cp.async.cg.shared.global [%0], [%1], 16;\n" :: "r"(sa), "l"(g));
}
__device__ __forceinline__ void cp_commit() {
    asm volatile("cp.async.commit_group;\n");
}
template <int N> __device__ __forceinline__ void cp_wait() {
    asm volatile("cp.async.wait_group %0;\n" :: "n"(N));
}
__device__ __forceinline__ uint32_t smem_u32(const void* p) {
    return (uint32_t)__cvta_generic_to_shared((void*)p);
}

// ---------------------------------------------------------------------------
// Weight fp32 -> fp16 conversion
// ---------------------------------------------------------------------------
__global__ void w2h_kernel(const float* __restrict__ s, __half* __restrict__ d, int n) {
    int i = (blockIdx.x * blockDim.x + threadIdx.x) * 4;
    if (i < n) {
        float4 v = *(const float4*)(s + i);
        __half2 h0 = __floats2half2_rn(v.x, v.y);
        __half2 h1 = __floats2half2_rn(v.z, v.w);
        *(__half2*)(d + i)     = h0;
        *(__half2*)(d + i + 2) = h1;
    }
}

// ---------------------------------------------------------------------------
// SiLU(cond)
// ---------------------------------------------------------------------------
__global__ void silu_kernel(const float* __restrict__ cond) {
    int i = blockIdx.x * blockDim.x + threadIdx.x;
    if (i < Bn * Ddim) {
        float v = cond[i];
        g_silu[i] = v / (1.f + expf(-v));
    }
}

// ---------------------------------------------------------------------------
// ada = silu(cond) @ ada_w^T + ada_b  (fp32 GEMV)
// ---------------------------------------------------------------------------
__global__ void ada_kernel(const float* __restrict__ ada_w,
                           const float* __restrict__ ada_b) {
    int gw   = (blockIdx.x * blockDim.x + threadIdx.x) >> 5;
    int lane = threadIdx.x & 31;
    if (gw >= Bn * 6 * Cdim) return;
    int b = gw / (6 * Cdim), j = gw % (6 * Cdim);
    const float* wv = ada_w + (size_t)j * Ddim;
    const float* sv = g_silu + b * Ddim;
    float acc = 0.f;
    #pragma unroll 2
    for (int i = lane * 4; i < Ddim; i += 128) {
        float4 w4 = *(const float4*)(wv + i);
        float4 s4 = *(const float4*)(sv + i);
        acc += w4.x * s4.x + w4.y * s4.y + w4.z * s4.z + w4.w * s4.w;
    }
    acc = warp_sum(acc);
    if (lane == 0) g_ada[b * 6 * Cdim + j] = acc + ada_b[j];
}

// ---------------------------------------------------------------------------
// h = LN(x) * (s+1) + sh   -> half
// ---------------------------------------------------------------------------
__global__ void ln_mod_kernel(const float* __restrict__ x, __half* __restrict__ h,
                              int sChunk, int shChunk) {
    __shared__ float red[32];
    int row = blockIdx.x;
    int b   = row >> 11;
    const float* xr = x + (size_t)row * Cdim;
    int c = threadIdx.x * 4;
    float4 v = *(const float4*)(xr + c);
    float tot  = block_sum(v.x + v.y + v.z + v.w, red);
    float mean = tot * (1.f / Cdim);
    float dx = v.x - mean, dy = v.y - mean, dz = v.z - mean, dw = v.w - mean;
    float tss  = block_sum(dx * dx + dy * dy + dz * dz + dw * dw, red);
    float rstd = rsqrtf(tss * (1.f / Cdim) + LN_EPS);
    const float* sP  = g_ada + b * 6 * Cdim + sChunk  * Cdim;
    const float* shP = g_ada + b * 6 * Cdim + shChunk * Cdim;
    float4 s4  = *(const float4*)(sP  + c);
    float4 sh4 = *(const float4*)(shP + c);
    __half2 o0 = __floats2half2_rn(dx * rstd * (s4.x + 1.f) + sh4.x,
                                   dy * rstd * (s4.y + 1.f) + sh4.y);
    __half2 o1 = __floats2half2_rn(dz * rstd * (s4.z + 1.f) + sh4.z,
                                   dw * rstd * (s4.w + 1.f) + sh4.w);
    *(__half2*)(h + (size_t)row * Cdim + c)     = o0;
    *(__half2*)(h + (size_t)row * Cdim + c + 2) = o1;
}

// ---------------------------------------------------------------------------
// FP16 tensor-core GEMM (m16n8k16 + ldmatrix), 3-stage cp.async.
// C[M,N] = A[M,K] @ W[N,K]^T (+ fused epilogue)
// Block 128x128, BK=32 halves, 4 warps 2(M)x2(N), warp tile 64x64.
//   MODE 0: QKV->half  MODE 1: PROJ->float  MODE 2: FC1+GELU->half  MODE 3: FC2->float(in place)
// ---------------------------------------------------------------------------
#define GSTAGES 3
#define GPADH 40                 // halves per row (32 data + 8 pad) = 80B
#define GTILEH (128 * GPADH)

template <int MODE>
__global__ __launch_bounds__(128, 2)
void gemm_h(const __half* __restrict__ A, const __half* __restrict__ W,
            void* __restrict__ Cout, int M, int N, int K,
            const float* __restrict__ bias,
            const float* __restrict__ bias2,
            const float* __restrict__ res) {
    extern __shared__ __half hsm[];
    __half* AsB = hsm;
    __half* WsB = hsm + GSTAGES * GTILEH;

    const int tid  = threadIdx.x;
    const int lane = tid & 31;
    const int warp = tid >> 5;
    const int wm   = (warp & 1) * 64;
    const int wn   = (warp >> 1) * 64;
    const int gid  = lane >> 2;
    const int tig  = lane & 3;
    const int m0 = blockIdx.y * 128, n0 = blockIdx.x * 128;

    // fragment ldmatrix lane-addressing (halves)
    const int a_row = (lane & 15);              // + wm + mt*16
    const int a_col = (lane >> 4) << 3;         // + ks
    const int b_row = ((lane >> 4) << 3) + (lane & 7);   // + wn + p*16
    const int b_col = ((lane >> 3) & 1) << 3;   // + ks

    float c[4][8][4];
    #pragma unroll
    for (int i = 0; i < 4; i++)
        #pragma unroll
        for (int j = 0; j < 8; j++)
            #pragma unroll
            for (int q = 0; q < 4; q++) c[i][j][q] = 0.f;

    const int ktotal = K >> 5;                  // BK=32

    auto stage = [&](int s, int slot) {
        __half* As = AsB + slot * GTILEH;
        __half* Ws = WsB + slot * GTILEH;
        int kt = s << 5;
        #pragma unroll
        for (int i = 0; i < 4; i++) {
            int idx = tid + i * 128;            // 0..511
            int row = idx >> 2;                 // 0..127
            int ch  = (idx & 3) << 3;           // halves: 0,8,16,24
            cp16(&As[row * GPADH + ch], A + (size_t)(m0 + row) * K + kt + ch);
            cp16(&Ws[row * GPADH + ch], W + (size_t)(n0 + row) * K + kt + ch);
        }
    };

    stage(0, 0); cp_commit();
    stage(1, 1); cp_commit();
    cp_wait<1>();
    __syncthreads();

    for (int s = 0; s < ktotal; s++) {
        int nxt = s + 2;
        if (nxt < ktotal) stage(nxt, nxt % GSTAGES);
        cp_commit();

        const __half* As = AsB + (s % GSTAGES) * GTILEH;
        const __half* Ws = WsB + (s % GSTAGES) * GTILEH;
        #pragma unroll
        for (int ks = 0; ks < 32; ks += 16) {
            unsigned a[4][4], b[4][4];
            #pragma unroll
            for (int mt = 0; mt < 4; mt++)
                ldm4(a[mt], smem_u32(&As[(wm + mt * 16 + a_row) * GPADH + ks + a_col]));
            #pragma unroll
            for (int p = 0; p < 4; p++)
                ldm4(b[p], smem_u32(&Ws[(wn + p * 16 + b_row) * GPADH + ks + b_col]));
            #pragma unroll
            for (int mt = 0; mt < 4; mt++)
                #pragma unroll
                for (int p = 0; p < 4; p++) {
                    mma_f16(c[mt][2 * p],     a[mt], b[p][0], b[p][1]);
                    mma_f16(c[mt][2 * p + 1], a[mt], b[p][2], b[p][3]);
                }
        }
        cp_wait<1>();
        __syncthreads();
    }

    const int b_idx = m0 >> 11;
    #pragma unroll
    for (int mt = 0; mt < 4; mt++) {
        #pragma unroll
        for (int half_ = 0; half_ < 2; half_++) {
            int row = m0 + wm + mt * 16 + gid + half_ * 8;
            #pragma unroll
            for (int nt = 0; nt < 8; nt++) {
                int col = n0 + wn + nt * 8 + tig * 2;
                float v0 = c[mt][nt][half_ * 2];
                float v1 = c[mt][nt][half_ * 2 + 1];
                if (MODE == 0) {
                    float bb0 = (col < Cdim) ? bias[col]
                              : (col < 2 * Cdim) ? 0.f : bias2[col - 2 * Cdim];
                    int col1 = col + 1;
                    float bb1 = (col1 < Cdim) ? bias[col1]
                              : (col1 < 2 * Cdim) ? 0.f : bias2[col1 - 2 * Cdim];
                    *(__half2*)((__half*)Cout + (size_t)row * N + col) =
                        __floats2half2_rn(v0 + bb0, v1 + bb1);
                } else if (MODE == 1) {
                    float gg0 = g_ada[b_idx * 6 * Cdim + col];
                    float gg1 = g_ada[b_idx * 6 * Cdim + col + 1];
                    const float* rp = res + (size_t)row * Cdim + col;
                    float2 o2;
                    o2.x = rp[0] + (v0 + bias[col])     * gg0;
                    o2.y = rp[1] + (v1 + bias[col + 1]) * gg1;
                    *(float2*)((float*)Cout + (size_t)row * N + col) = o2;
                } else if (MODE == 2) {
                    float xg0 = v0 + bias[col];
                    float xg1 = v1 + bias[col + 1];
                    float t0 = tanhf(0.7978845608028654f * (xg0 + 0.044715f * xg0 * xg0 * xg0));
                    float t1 = tanhf(0.7978845608028654f * (xg1 + 0.044715f * xg1 * xg1 * xg1));
                    *(__half2*)((__half*)Cout + (size_t)row * N + col) =
                        __floats2half2_rn(0.5f * xg0 * (1.f + t0), 0.5f * xg1 * (1.f + t1));
                } else {
                    float gg0 = g_ada[b_idx * 6 * Cdim + Cdim + col];
                    float gg1 = g_ada[b_idx * 6 * Cdim + Cdim + col + 1];
                    float* cp = (float*)Cout + (size_t)row * N + col;
                    float2 cur = *(float2*)cp;
                    float2 o2;
                    o2.x = cur.x + (v0 + bias[col])     * gg0;
                    o2.y = cur.y + (v1 + bias[col + 1]) * gg1;
                    *(float2*)cp = o2;
                }
            }
        }
    }
}

// ---------------------------------------------------------------------------
// Normalize q,k per (row, head) on half data
// ---------------------------------------------------------------------------
__global__ void norm_qk_kernel(const float* __restrict__ scale_mul) {
    int gw   = (blockIdx.x * blockDim.x + threadIdx.x) >> 5;
    int lane = threadIdx.x & 31;
    if (gw >= ROWS * Hn) return;
    int row = gw >> 4, h = gw & 15;
    float sm = expf(fminf(scale_mul[h], MAX_SCALE_MUL));
    __half* q = g_qkv + (size_t)row * (3 * Cdim) + h * DH;
    __half* k = q + Cdim;

    float2 qv = __half22float2(*(__half2*)(q + lane * 2));
    float  sq = warp_sum(qv.x * qv.x + qv.y * qv.y);
    float  rq = rsqrtf(fmaxf(sq, 1e-24f)) * sm;
    *(__half2*)(q + lane * 2) = __floats2half2_rn(qv.x * rq, qv.y * rq);

    float2 kv = __half22float2(*(__half2*)(k + lane * 2));
    float  sk = warp_sum(kv.x * kv.x + kv.y * kv.y);
    float  rk = rsqrtf(fmaxf(sk, 1e-24f));
    *(__half2*)(k + lane * 2) = __floats2half2_rn(kv.x * rk, kv.y * rk);
}

// ---------------------------------------------------------------------------
// FP16 flash attention: m16n8k16 + ldmatrix; P reuses S fragment layout.
// Block: 128 q-rows x (h, b). 8 warps x 16 q-rows. KV tiles 64, double buffer.
// smem halves: Q[128][72], K[2][64][72], V[2][64][72]  (72*2=144B stride)
// ---------------------------------------------------------------------------
#define AQT 128
#define AKT 64
#define ASTRH 72
#define AKVH (AKT * ASTRH)

__global__ __launch_bounds__(256)
void attn_h_kernel(const float* __restrict__ attn_bias) {
    extern __shared__ __half ahsm[];
    __half* Qs  = ahsm;
    __half* KsB = Qs + AQT * ASTRH;
    __half* VsB = KsB + 2 * AKVH;

    const int tid  = threadIdx.x;
    const int lane = tid & 31;
    const int w    = tid >> 5;
    const int gid  = lane >> 2;
    const int tig  = lane & 3;
    const int qt = blockIdx.x, h = blockIdx.y, b = blockIdx.z;
    const int qbase = b * Ln + qt * AQT;
    const int NTILES = Ln / AKT;

    const int a_row = (lane & 15);
    const int a_col = (lane >> 4) << 3;
    const int b_row = ((lane >> 4) << 3) + (lane & 7);
    const int b_col = ((lane >> 3) & 1) << 3;
    const int v_row = (((lane >> 3) & 1) << 3) + (lane & 7);
    const int v_col = (lane >> 4) << 3;

    auto stage_kv = [&](int it, int slot) {
        int kbase = b * Ln + it * AKT;
        __half* Ks = KsB + slot * AKVH;
        __half* Vs = VsB + slot * AKVH;
        #pragma unroll
        for (int r = 0; r < 2; r++) {
            int idx = tid + r * 256;            // 0..511
            int kr  = idx >> 3;
            int ch  = (idx & 7) << 3;           // halves
            size_t base = (size_t)(kbase + kr) * (3 * Cdim) + h * DH + ch;
            cp16(&Ks[kr * ASTRH + ch], g_qkv + base + Cdim);
            cp16(&Vs[kr * ASTRH + ch], g_qkv + base + 2 * Cdim);
        }
    };

    stage_kv(0, 0); cp_commit();

    // Stage Q (direct)
    #pragma unroll
    for (int r = 0; r < 4; r++) {
        int idx = tid + r * 256;                // 0..1023
        int qr  = idx >> 3;
        int ch  = (idx & 7) << 3;
        uint4 v = *(const uint4*)(g_qkv + (size_t)(qbase + qr) * (3 * Cdim) + h * DH + ch);
        *(uint4*)&Qs[qr * ASTRH + ch] = v;
    }
    __syncthreads();

    // Q fragments register-resident (4 k16-chunks over DH=64)
    unsigned qf[4][4];
    #pragma unroll
    for (int kc = 0; kc < 4; kc++)
        ldm4(qf[kc], smem_u32(&Qs[(w * 16 + a_row) * ASTRH + kc * 16 + a_col]));

    float m0r = -1e30f, m1r = -1e30f, l0 = 0.f, l1 = 0.f;
    float o[8][4];
    #pragma unroll
    for (int nt = 0; nt < 8; nt++)
        #pragma unroll
        for (int i = 0; i < 4; i++) o[nt][i] = 0.f;

    const int gq0 = qt * AQT + w * 16 + gid;

    for (int it = 0; it < NTILES; it++) {
        if (it + 1 < NTILES) stage_kv(it + 1, (it + 1) & 1);
        cp_commit();
        cp_wait<1>();
        __syncthreads();

        const __half* Ks = KsB + (it & 1) * AKVH;
        const __half* Vs = VsB + (it & 1) * AKVH;

        // S = Q K^T + bias
        float s[8][4];
        const float* bias0 = attn_bias + (size_t)gq0 * Ln + it * AKT;
        #pragma unroll
        for (int p = 0; p < 4; p++) {           // nt pairs
            #pragma unroll
            for (int i = 0; i < 4; i++) { s[2 * p][i] = 0.f; s[2 * p + 1][i] = 0.f; }
            #pragma unroll
            for (int kc = 0; kc < 4; kc++) {
                unsigned kb[4];
                ldm4(kb, smem_u32(&Ks[(p * 16 + b_row) * ASTRH + kc * 16 + b_col]));
                mma_f16(s[2 * p],     qf[kc], kb[0], kb[1]);
                mma_f16(s[2 * p + 1], qf[kc], kb[2], kb[3]);
            }
        }
        #pragma unroll
        for (int nt = 0; nt < 8; nt++) {
            float2 b0 = *(const float2*)(bias0 + nt * 8 + tig * 2);
            float2 b1 = *(const float2*)(bias0 + 8 * Ln + nt * 8 + tig * 2);
            s[nt][0] += b0.x; s[nt][1] += b0.y;
            s[nt][2] += b1.x; s[nt][3] += b1.y;
        }

        // online softmax (fp32)
        float mx0 = -1e30f, mx1 = -1e30f;
        #pragma unroll
        for (int nt = 0; nt < 8; nt++) {
            mx0 = fmaxf(mx0, fmaxf(s[nt][0], s[nt][1]));
            mx1 = fmaxf(mx1, fmaxf(s[nt][2], s[nt][3]));
        }
        mx0 = fmaxf(mx0, __shfl_xor_sync(FULLM, mx0, 1));
        mx0 = fmaxf(mx0, __shfl_xor_sync(FULLM, mx0, 2));
        mx1 = fmaxf(mx1, __shfl_xor_sync(FULLM, mx1, 1));
        mx1 = fmaxf(mx1, __shfl_xor_sync(FULLM, mx1, 2));
        float nm0 = fmaxf(m0r, mx0), nm1 = fmaxf(m1r, mx1);
        float al0 = __expf(m0r - nm0), al1 = __expf(m1r - nm1);
        m0r = nm0; m1r = nm1;

        float sum0 = 0.f, sum1 = 0.f;
        #pragma unroll
        for (int nt = 0; nt < 8; nt++) {
            s[nt][0] = __expf(s[nt][0] - nm0);
            s[nt][1] = __expf(s[nt][1] - nm0);
            s[nt][2] = __expf(s[nt][2] - nm1);
            s[nt][3] = __expf(s[nt][3] - nm1);
            sum0 += s[nt][0] + s[nt][1];
            sum1 += s[nt][2] + s[nt][3];
        }
        sum0 += __shfl_xor_sync(FULLM, sum0, 1);
        sum0 += __shfl_xor_sync(FULLM, sum0, 2);
        sum1 += __shfl_xor_sync(FULLM, sum1, 1);
        sum1 += __shfl_xor_sync(FULLM, sum1, 2);
        l0 = l0 * al0 + sum0;
        l1 = l1 * al1 + sum1;
        #pragma unroll
        for (int nt = 0; nt < 8; nt++) {
            o[nt][0] *= al0; o[nt][1] *= al0;
            o[nt][2] *= al1; o[nt][3] *= al1;
        }

        // P fragments: S accumulator layout IS the fp16 A-fragment layout
        unsigned pf[4][4];
        #pragma unroll
        for (int kc = 0; kc < 4; kc++) {
            pf[kc][0] = packh2(s[2 * kc][0],     s[2 * kc][1]);
            pf[kc][1] = packh2(s[2 * kc][2],     s[2 * kc][3]);
            pf[kc][2] = packh2(s[2 * kc + 1][0], s[2 * kc + 1][1]);
            pf[kc][3] = packh2(s[2 * kc + 1][2], s[2 * kc + 1][3]);
        }

        // O += P V  (V via ldmatrix.trans)
        #pragma unroll
        for (int p = 0; p < 4; p++) {           // dh n-pairs
            #pragma unroll
            for (int kc = 0; kc < 4; kc++) {
                unsigned vb[4];
                ldm4t(vb, smem_u32(&Vs[(kc * 16 + v_row) * ASTRH + p * 16 + v_col]));
                mma_f16(o[2 * p],     pf[kc], vb[0], vb[1]);
                mma_f16(o[2 * p + 1], pf[kc], vb[2], vb[3]);
            }
        }
        __syncthreads();
    }

    float inv0 = 1.f / l0, inv1 = 1.f / l1;
    int row0 = qbase + w * 16 + gid;
    #pragma unroll
    for (int nt = 0; nt < 8; nt++) {
        int col = h * DH + nt * 8 + tig * 2;
        *(__half2*)(g_attn + (size_t)row0 * Cdim + col) =
            __floats2half2_rn(o[nt][0] * inv0, o[nt][1] * inv0);
        *(__half2*)(g_attn + (size_t)(row0 + 8) * Cdim + col) =
            __floats2half2_rn(o[nt][2] * inv1, o[nt][3] * inv1);
    }
}

// ---------------------------------------------------------------------------
// Launch
// ---------------------------------------------------------------------------
extern "C" void kernel_launch(void* const* d_in, const int* in_sizes, int n_in,
                              void* d_out, int out_size) {
    const float* x         = (const float*)d_in[0];
    const float* cond      = (const float*)d_in[1];
    const float* attn_bias = (const float*)d_in[2];
    const float* qkv_w     = (const float*)d_in[3];
    const float* q_bias    = (const float*)d_in[4];
    const float* v_bias    = (const float*)d_in[5];
    const float* scale_mul = (const float*)d_in[6];
    const float* proj_w    = (const float*)d_in[7];
    const float* proj_b    = (const float*)d_in[8];
    const float* fc1_w     = (const float*)d_in[9];
    const float* fc1_b     = (const float*)d_in[10];
    const float* fc2_w     = (const float*)d_in[11];
    const float* fc2_b     = (const float*)d_in[12];
    const float* ada_w     = (const float*)d_in[13];
    const float* ada_b     = (const float*)d_in[14];
    float* out = (float*)d_out;

    __half *wqkvP, *wprojP, *wfc1P, *wfc2P, *ghP, *gqkvP, *gattnP, *gffnP;
    cudaGetSymbolAddress((void**)&wqkvP,  g_wqkv);
    cudaGetSymbolAddress((void**)&wprojP, g_wproj);
    cudaGetSymbolAddress((void**)&wfc1P,  g_wfc1);
    cudaGetSymbolAddress((void**)&wfc2P,  g_wfc2);
    cudaGetSymbolAddress((void**)&ghP,    g_h);
    cudaGetSymbolAddress((void**)&gqkvP,  g_qkv);
    cudaGetSymbolAddress((void**)&gattnP, g_attn);
    cudaGetSymbolAddress((void**)&gffnP,  g_ffn);

    int gemm_smem = 2 * GSTAGES * GTILEH * (int)sizeof(__half);     // 61440
    cudaFuncSetAttribute(gemm_h<0>, cudaFuncAttributeMaxDynamicSharedMemorySize, gemm_smem);
    cudaFuncSetAttribute(gemm_h<1>, cudaFuncAttributeMaxDynamicSharedMemorySize, gemm_smem);
    cudaFuncSetAttribute(gemm_h<2>, cudaFuncAttributeMaxDynamicSharedMemorySize, gemm_smem);
    cudaFuncSetAttribute(gemm_h<3>, cudaFuncAttributeMaxDynamicSharedMemorySize, gemm_smem);
    int attn_smem = (AQT * ASTRH + 4 * AKVH) * (int)sizeof(__half); // 55296
    cudaFuncSetAttribute(attn_h_kernel, cudaFuncAttributeMaxDynamicSharedMemorySize, attn_smem);

    // 0) convert weights to half
    w2h_kernel<<<(3 * Cdim * Cdim / 4 + 255) / 256, 256>>>(qkv_w, wqkvP, 3 * Cdim * Cdim);
    w2h_kernel<<<(Cdim * Cdim / 4 + 255) / 256, 256>>>(proj_w, wprojP, Cdim * Cdim);
    w2h_kernel<<<(DFF * Cdim / 4 + 255) / 256, 256>>>(fc1_w, wfc1P, DFF * Cdim);
    w2h_kernel<<<(Cdim * DFF / 4 + 255) / 256, 256>>>(fc2_w, wfc2P, Cdim * DFF);
    // 1) SiLU(cond)
    silu_kernel<<<(Bn * Ddim + 255) / 256, 256>>>(cond);
    // 2) adaLN linear
    ada_kernel<<<(Bn * 6 * Cdim * 32 + 255) / 256, 256>>>(ada_w, ada_b);
    // 3) h = LN(x)*(s1+1)+sh1
    ln_mod_kernel<<<ROWS, 256>>>(x, ghP, 2, 4);
    // 4) qkv = h @ qkv_w^T + bias
    gemm_h<0><<<dim3(3 * Cdim / 128, ROWS / 128), 128, gemm_smem>>>(
        ghP, wqkvP, gqkvP, ROWS, 3 * Cdim, Cdim, q_bias, v_bias, nullptr);
    // 5) normalize q,k
    norm_qk_kernel<<<(ROWS * Hn * 32 + 255) / 256, 256>>>(scale_mul);
    // 6) attention
    attn_h_kernel<<<dim3(Ln / AQT, Hn, Bn), 256, attn_smem>>>(attn_bias);
    // 7) x1 = x + (attn @ proj_w^T + proj_b) * g1 -> d_out (fp32)
    gemm_h<1><<<dim3(Cdim / 128, ROWS / 128), 128, gemm_smem>>>(
        gattnP, wprojP, out, ROWS, Cdim, Cdim, proj_b, nullptr, x);
    // 8) h = LN(x1)*(s2+1)+sh2
    ln_mod_kernel<<<ROWS, 256>>>(out, ghP, 3, 5);
    // 9) ffn = gelu(h @ fc1_w^T + fc1_b) -> half
    gemm_h<2><<<dim3(DFF / 128, ROWS / 128), 128, gemm_smem>>>(
        ghP, wfc1P, gffnP, ROWS, DFF, Cdim, fc1_b, nullptr, nullptr);
    // 10) out += (ffn @ fc2_w^T + fc2_b) * g2
    gemm_h<3><<<dim3(Cdim / 128, ROWS / 128), 128, gemm_smem>>>(
        gffnP, wfc2P, out, ROWS, Cdim, DFF, fc2_b, nullptr, nullptr);
}